// round 10
// baseline (speedup 1.0000x reference)
#include <cuda_runtime.h>
#include <cuda_fp16.h>
#include <cstdint>

#define M_DIM 8192
#define N_DIM 8192
#define IN_DIM 128
#define HID 256
#define TOPK 512
#define WINBINS 512
#define CAND_CAP (1 << 16)
#define NTILES (128 * 256)   // 64x32 warp tiles

// ---------------- device scratch (no allocations allowed) ----------------
__device__ __half g_md0h[M_DIM * HID];
__device__ __half g_md0l[M_DIM * HID];
__device__ __half g_md1h[N_DIM * HID];
__device__ __half g_md1l[N_DIM * HID];
__device__ float g_md0f[M_DIM * HID];
__device__ float g_md1f[N_DIM * HID];
__device__ unsigned short g_key16[(size_t)M_DIM * N_DIM];  // compact sort keys
__device__ unsigned short g_tilemax[NTILES];               // per 64x32 tile key max
__device__ unsigned int g_hist[WINBINS];
__device__ unsigned int g_maxkey;
__device__ unsigned int g_cutabs;   // 16-bit key threshold
__device__ unsigned int g_cand_count;
__device__ unsigned int g_cand_idx[CAND_CAP];
__device__ double g_cand_ref[CAND_CAP];

__device__ __forceinline__ unsigned int fkey(float v) {
    unsigned int u = __float_as_uint(v);
    return (u & 0x80000000u) ? ~u : (u | 0x80000000u);
}

// ---------------- reset ----------------
__global__ void reset_kernel() {
    int t = threadIdx.x;
    if (t < WINBINS) g_hist[t] = 0;
    if (t == 0) { g_maxkey = 0; g_cand_count = 0; }
}

// ---------------- MLP (both descriptors in one grid) ----------------
__global__ void __launch_bounds__(256) mlp_kernel(
    const float* __restrict__ x0, const float* __restrict__ x1,
    const float* __restrict__ W0a, const float* __restrict__ b0a,
    const float* __restrict__ W0b, const float* __restrict__ b0b,
    const float* __restrict__ W1a, const float* __restrict__ b1a,
    const float* __restrict__ W1b, const float* __restrict__ b1b)
{
    __shared__ float xs[32 * IN_DIM];
    __shared__ float hs[32 * HID];
    int which = (blockIdx.x >= 256) ? 1 : 0;
    int blk = blockIdx.x & 255;
    const float* x = which ? x1 : x0;
    const float* Wa = which ? W1a : W0a;
    const float* ba = which ? b1a : b0a;
    const float* Wb = which ? W1b : W0b;
    const float* bb = which ? b1b : b0b;
    __half* outh = which ? g_md1h : g_md0h;
    __half* outl = which ? g_md1l : g_md0l;
    float* outf = which ? g_md1f : g_md0f;

    int tid = threadIdx.x;
    const float* xb = x + (size_t)blk * 32 * IN_DIM;

    {
        const float4* src = (const float4*)xb;
        float4* dst = (float4*)xs;
        for (int i = tid; i < 32 * IN_DIM / 4; i += 256) dst[i] = src[i];
    }
    __syncthreads();

    float acc[32];
    float bav = ba[tid];
#pragma unroll
    for (int r = 0; r < 32; r++) acc[r] = bav;

    const float4* xs4 = (const float4*)xs;
    for (int k = 0; k < IN_DIM; k += 4) {
        float w0 = Wa[(k + 0) * HID + tid];
        float w1 = Wa[(k + 1) * HID + tid];
        float w2 = Wa[(k + 2) * HID + tid];
        float w3 = Wa[(k + 3) * HID + tid];
#pragma unroll
        for (int r = 0; r < 32; r++) {
            float4 xv = xs4[r * (IN_DIM / 4) + (k >> 2)];
            acc[r] += xv.x * w0; acc[r] += xv.y * w1;
            acc[r] += xv.z * w2; acc[r] += xv.w * w3;
        }
    }
#pragma unroll
    for (int r = 0; r < 32; r++) hs[r * HID + tid] = fmaxf(acc[r], 0.0f);
    __syncthreads();

    float bbv = bb[tid];
#pragma unroll
    for (int r = 0; r < 32; r++) acc[r] = bbv;

    const float4* hs4 = (const float4*)hs;
    for (int k = 0; k < HID; k += 4) {
        float w0 = Wb[(k + 0) * HID + tid];
        float w1 = Wb[(k + 1) * HID + tid];
        float w2 = Wb[(k + 2) * HID + tid];
        float w3 = Wb[(k + 3) * HID + tid];
#pragma unroll
        for (int r = 0; r < 32; r++) {
            float4 hv = hs4[r * (HID / 4) + (k >> 2)];
            acc[r] += hv.x * w0; acc[r] += hv.y * w1;
            acc[r] += hv.z * w2; acc[r] += hv.w * w3;
        }
    }
#pragma unroll
    for (int r = 0; r < 32; r++) {
        float v = acc[r];
        __half hi = __float2half_rn(v);
        __half lo = __float2half_rn(v - __half2float(hi));
        size_t o = ((size_t)blk * 32 + r) * HID + tid;
        outh[o] = hi;
        outl[o] = lo;
        outf[o] = v;
    }
}

// ---------------- fp16 3-term NT GEMM, BK=32, 2 CTAs/SM, key16 + tilemax side outputs ----------------
#define BK 32
#define PITCH 40                       // halves per smem row (80B: 20-word rows -> 4-bank skew)
#define ROWB (PITCH * 2)               // 80 bytes
#define PLANE_BYTES (128 * ROWB)       // 10240
#define BUF_BYTES (4 * PLANE_BYTES)    // 40960 (Ah, Al, Bh, Bl)
#define GSMEM_BYTES (2 * BUF_BYTES)    // 81920 -> 2 CTAs/SM

__device__ __forceinline__ uint32_t smem_u32(const void* p) {
    uint32_t a;
    asm("{ .reg .u64 t; cvta.to.shared.u64 t, %1; cvt.u32.u64 %0, t; }" : "=r"(a) : "l"(p));
    return a;
}
__device__ __forceinline__ void cp16(uint32_t dst, const void* src) {
    asm volatile("cp.async.cg.shared.global [%0], [%1], 16;" :: "r"(dst), "l"(src) : "memory");
}
__device__ __forceinline__ void cp_commit() { asm volatile("cp.async.commit_group;" ::: "memory"); }
template <int N>
__device__ __forceinline__ void cp_wait() { asm volatile("cp.async.wait_group %0;" :: "n"(N) : "memory"); }

__device__ __forceinline__ void ldsm_x4(uint32_t& r0, uint32_t& r1, uint32_t& r2, uint32_t& r3,
                                        uint32_t addr) {
    asm volatile("ldmatrix.sync.aligned.m8n8.x4.shared.b16 {%0,%1,%2,%3}, [%4];"
                 : "=r"(r0), "=r"(r1), "=r"(r2), "=r"(r3) : "r"(addr));
}
__device__ __forceinline__ void ldsm_x2(uint32_t& r0, uint32_t& r1, uint32_t addr) {
    asm volatile("ldmatrix.sync.aligned.m8n8.x2.shared.b16 {%0,%1}, [%2];"
                 : "=r"(r0), "=r"(r1) : "r"(addr));
}

__device__ __forceinline__ void mma16816(float* d, uint32_t a0, uint32_t a1, uint32_t a2,
                                         uint32_t a3, uint32_t b0, uint32_t b1) {
    asm volatile(
        "mma.sync.aligned.m16n8k16.row.col.f32.f16.f16.f32 "
        "{%0,%1,%2,%3}, {%4,%5,%6,%7}, {%8,%9}, {%0,%1,%2,%3};"
        : "+f"(d[0]), "+f"(d[1]), "+f"(d[2]), "+f"(d[3])
        : "r"(a0), "r"(a1), "r"(a2), "r"(a3), "r"(b0), "r"(b1));
}

__global__ void __launch_bounds__(256, 2) gemm_mma_kernel(float* __restrict__ C) {
    extern __shared__ char smem[];
    uint32_t sb = smem_u32(smem);

    int tid = threadIdx.x;
    int wid = tid >> 5;
    int lane = tid & 31;
    int gid = lane >> 2;
    int tig = lane & 3;
    int m0 = blockIdx.y * 128;
    int n0 = blockIdx.x * 128;
    int wm = (wid >> 2) * 64;
    int wn = (wid & 3) * 32;

    float acc[4][4][4];
#pragma unroll
    for (int i = 0; i < 4; i++)
#pragma unroll
        for (int j = 0; j < 4; j++)
#pragma unroll
            for (int k = 0; k < 4; k++) acc[i][j][k] = 0.0f;

    const __half* planes_g[4] = {g_md0h, g_md0l, g_md1h, g_md1l};

    auto issue_chunk = [&](int kc, int buf) {
        uint32_t base = sb + buf * BUF_BYTES;
#pragma unroll
        for (int p = 0; p < 4; p++) {
            const __half* gp = planes_g[p];
            int row0 = (p < 2) ? m0 : n0;
#pragma unroll
            for (int j = 0; j < 2; j++) {
                int chunk = tid * 2 + j;       // 0..511
                int row = chunk >> 2;
                int seg = chunk & 3;           // 16B segment within 64B row
                uint32_t dst = base + p * PLANE_BYTES + row * ROWB + seg * 16;
                const void* src = gp + (size_t)(row0 + row) * HID + kc * BK + seg * 8;
                cp16(dst, src);
            }
        }
        cp_commit();
    };

    int a_rowadd = (lane & 7) + ((lane >> 3) & 1) * 8;
    int a_seg = (lane >> 4) * 16;
    int b_lane = lane & 15;
    int b_rowadd = b_lane & 7;
    int b_seg = ((b_lane >> 3) & 1) * 16;

    issue_chunk(0, 0);

    const int NCH = HID / BK;  // 8
    for (int kc = 0; kc < NCH; kc++) {
        int buf = kc & 1;
        if (kc + 1 < NCH) {
            issue_chunk(kc + 1, (kc + 1) & 1);
            cp_wait<1>();
        } else {
            cp_wait<0>();
        }
        __syncthreads();

        uint32_t bufb = sb + buf * BUF_BYTES;
        uint32_t pAh = bufb + 0 * PLANE_BYTES;
        uint32_t pAl = bufb + 1 * PLANE_BYTES;
        uint32_t pBh = bufb + 2 * PLANE_BYTES;
        uint32_t pBl = bufb + 3 * PLANE_BYTES;

#pragma unroll
        for (int ks = 0; ks < BK / 16; ks++) {
            uint32_t kso = ks * 32;
            uint32_t ah[4][4], al[4][4], bh[4][2], bl[4][2];
#pragma unroll
            for (int mt = 0; mt < 4; mt++) {
                uint32_t ro = (uint32_t)(wm + mt * 16 + a_rowadd) * ROWB + kso + a_seg;
                ldsm_x4(ah[mt][0], ah[mt][1], ah[mt][2], ah[mt][3], pAh + ro);
                ldsm_x4(al[mt][0], al[mt][1], al[mt][2], al[mt][3], pAl + ro);
            }
#pragma unroll
            for (int nt = 0; nt < 4; nt++) {
                uint32_t ro = (uint32_t)(wn + nt * 8 + b_rowadd) * ROWB + kso + b_seg;
                ldsm_x2(bh[nt][0], bh[nt][1], pBh + ro);
                ldsm_x2(bl[nt][0], bl[nt][1], pBl + ro);
            }
#pragma unroll
            for (int mt = 0; mt < 4; mt++)
#pragma unroll
                for (int nt = 0; nt < 4; nt++) {
                    mma16816(acc[mt][nt], ah[mt][0], ah[mt][1], ah[mt][2], ah[mt][3],
                             bh[nt][0], bh[nt][1]);
                    mma16816(acc[mt][nt], ah[mt][0], ah[mt][1], ah[mt][2], ah[mt][3],
                             bl[nt][0], bl[nt][1]);
                    mma16816(acc[mt][nt], al[mt][0], al[mt][1], al[mt][2], al[mt][3],
                             bh[nt][0], bh[nt][1]);
                }
        }
        __syncthreads();
    }

    // epilogue: store C + packed key16 plane + tile max + fused global max
    unsigned int mymax = 0;
#pragma unroll
    for (int mt = 0; mt < 4; mt++) {
        int r0 = m0 + wm + mt * 16 + gid;
#pragma unroll
        for (int nt = 0; nt < 4; nt++) {
            int col = n0 + wn + nt * 8 + 2 * tig;
            size_t o0 = (size_t)r0 * N_DIM + col;
            size_t o1 = (size_t)(r0 + 8) * N_DIM + col;
            *(float2*)(C + o0) = make_float2(acc[mt][nt][0], acc[mt][nt][1]);
            *(float2*)(C + o1) = make_float2(acc[mt][nt][2], acc[mt][nt][3]);
            unsigned int k0 = fkey(acc[mt][nt][0]), k1 = fkey(acc[mt][nt][1]);
            unsigned int k2 = fkey(acc[mt][nt][2]), k3 = fkey(acc[mt][nt][3]);
            *(uint32_t*)(g_key16 + o0) = (k0 >> 16) | (k1 & 0xffff0000u);
            *(uint32_t*)(g_key16 + o1) = (k2 >> 16) | (k3 & 0xffff0000u);
            mymax = max(max(mymax, max(k0, k1)), max(k2, k3));
        }
    }
#pragma unroll
    for (int s = 16; s > 0; s >>= 1)
        mymax = max(mymax, __shfl_xor_sync(0xffffffffu, mymax, s));

    // warp tile max -> g_tilemax (tile = 64 rows x 32 cols)
    if (lane == 0) {
        int mt = blockIdx.y * 2 + (wid >> 2);   // 0..127
        int nt = blockIdx.x * 4 + (wid & 3);    // 0..255
        g_tilemax[mt * 256 + nt] = (unsigned short)(mymax >> 16);
    }

    __shared__ unsigned int wmax[8];
    if (lane == 0) wmax[wid] = mymax;
    __syncthreads();
    if (tid == 0) {
        unsigned int m = wmax[0];
#pragma unroll
        for (int i = 1; i < 8; i++) m = max(m, wmax[i]);
        atomicMax(&g_maxkey, m);
    }
}

// ---------------- tile-pruned windowed histogram (exact: sub-window tiles contribute nothing) ----------------
__global__ void hist_kernel() {
    unsigned int maxk16 = g_maxkey >> 16;
    unsigned int wcut = maxk16 - (WINBINS - 1);  // qualify if key >= wcut
    int lane = threadIdx.x & 31;
    int warp = (int)((blockIdx.x * blockDim.x + threadIdx.x) >> 5);
    int nwarp = (int)((gridDim.x * blockDim.x) >> 5);
    int r = lane >> 2, c4 = lane & 3;
    for (int base = warp * 32; base < NTILES; base += nwarp * 32) {
        unsigned int tm = g_tilemax[base + lane];
        unsigned int mask = __ballot_sync(0xffffffffu, tm >= wcut);
        while (mask) {
            int b = __ffs(mask) - 1;
            mask &= mask - 1;
            int tt = base + b;
            int m0 = (tt >> 8) * 64, n0 = (tt & 255) * 32;
            for (int rr = 0; rr < 64; rr += 8) {
                const uint4* p = (const uint4*)(g_key16 + (size_t)(m0 + rr + r) * N_DIM + n0 + c4 * 8);
                uint4 v = *p;
                unsigned int w[4] = {v.x, v.y, v.z, v.w};
#pragma unroll
                for (int j = 0; j < 4; j++) {
                    unsigned int rlo = maxk16 - (w[j] & 0xffffu);
                    unsigned int rhi = maxk16 - (w[j] >> 16);
                    if (rlo < WINBINS) atomicAdd(&g_hist[rlo], 1u);
                    if (rhi < WINBINS) atomicAdd(&g_hist[rhi], 1u);
                }
            }
        }
    }
}

// ---------------- find cut: parallel prefix scan over 512 bins, +1 bin margin ----------------
__global__ void __launch_bounds__(512) cut_kernel() {
    __shared__ unsigned int pfx[WINBINS];
    int t = threadIdx.x;
    pfx[t] = g_hist[t];
    __syncthreads();
    for (int off = 1; off < WINBINS; off <<= 1) {
        unsigned int v = (t >= off) ? pfx[t - off] : 0u;
        __syncthreads();
        pfx[t] += v;
        __syncthreads();
    }
    unsigned int maxk16 = g_maxkey >> 16;
    if (pfx[t] >= TOPK && (t == 0 || pfx[t - 1] < TOPK))
        g_cutabs = maxk16 - (unsigned int)(t + 1);   // +1 bin margin
    if (t == WINBINS - 1 && pfx[t] < TOPK)
        g_cutabs = maxk16 - (unsigned int)WINBINS;
}

// ---------------- tile-pruned candidate collection (exact) ----------------
__global__ void cand_kernel() {
    unsigned int cutabs = g_cutabs;
    int lane = threadIdx.x & 31;
    int warp = (int)((blockIdx.x * blockDim.x + threadIdx.x) >> 5);
    int nwarp = (int)((gridDim.x * blockDim.x) >> 5);
    int r = lane >> 2, c4 = lane & 3;
    for (int base = warp * 32; base < NTILES; base += nwarp * 32) {
        unsigned int tm = g_tilemax[base + lane];
        unsigned int mask = __ballot_sync(0xffffffffu, tm >= cutabs);
        while (mask) {
            int b = __ffs(mask) - 1;
            mask &= mask - 1;
            int tt = base + b;
            int m0 = (tt >> 8) * 64, n0 = (tt & 255) * 32;
            for (int rr = 0; rr < 64; rr += 8) {
                size_t rowoff = (size_t)(m0 + rr + r) * N_DIM + n0 + c4 * 8;
                const uint4* p = (const uint4*)(g_key16 + rowoff);
                uint4 v = *p;
                unsigned int w[4] = {v.x, v.y, v.z, v.w};
#pragma unroll
                for (int j = 0; j < 4; j++) {
                    if ((w[j] & 0xffffu) >= cutabs) {
                        unsigned int pos = atomicAdd(&g_cand_count, 1u);
                        if (pos < CAND_CAP) g_cand_idx[pos] = (unsigned int)(rowoff + 2 * j);
                    }
                    if ((w[j] >> 16) >= cutabs) {
                        unsigned int pos = atomicAdd(&g_cand_count, 1u);
                        if (pos < CAND_CAP) g_cand_idx[pos] = (unsigned int)(rowoff + 2 * j + 1);
                    }
                }
            }
        }
    }
}

// ---------------- refine: exact fp64 dot per candidate ----------------
__global__ void refine_kernel() {
    unsigned int count = g_cand_count;
    if (count > CAND_CAP) count = CAND_CAP;
    unsigned int warp = (blockIdx.x * blockDim.x + threadIdx.x) >> 5;
    unsigned int nwarp = (gridDim.x * blockDim.x) >> 5;
    int lane = threadIdx.x & 31;
    for (unsigned int c = warp; c < count; c += nwarp) {
        unsigned int idx = g_cand_idx[c];
        const float* a = g_md0f + (size_t)(idx >> 13) * HID;
        const float* b = g_md1f + (size_t)(idx & 8191u) * HID;
        double s = 0.0;
#pragma unroll
        for (int k = 0; k < HID / 32; k++)
            s += (double)a[k * 32 + lane] * (double)b[k * 32 + lane];
#pragma unroll
        for (int o = 16; o > 0; o >>= 1)
            s += __shfl_xor_sync(0xffffffffu, s, o);
        if (lane == 0) g_cand_ref[c] = s;
    }
}

// ---------------- rank-select on refined values (deterministic) ----------------
__global__ void __launch_bounds__(256) rank_kernel(float* __restrict__ idx_out) {
    unsigned int count = g_cand_count;
    if (count > CAND_CAP) count = CAND_CAP;
    unsigned int stride = gridDim.x * blockDim.x;
    for (unsigned int i = blockIdx.x * blockDim.x + threadIdx.x; i < count; i += stride) {
        double vi = g_cand_ref[i];
        unsigned int ii = g_cand_idx[i];
        unsigned int rank = 0;
        for (unsigned int j = 0; j < count; j++) {
            double vj = g_cand_ref[j];
            unsigned int ij = g_cand_idx[j];
            if (vj > vi || (vj == vi && ij < ii)) rank++;
        }
        if (rank < TOPK) {
            idx_out[rank * 2 + 0] = (float)(ii >> 13);
            idx_out[rank * 2 + 1] = (float)(ii & 8191u);
        }
    }
}

// ---------------- launch ----------------
extern "C" void kernel_launch(void* const* d_in, const int* in_sizes, int n_in,
                              void* d_out, int out_size) {
    const float* desc0 = (const float*)d_in[0];
    const float* desc1 = (const float*)d_in[1];
    const float* W0a = (const float*)d_in[2];
    const float* b0a = (const float*)d_in[3];
    const float* W0b = (const float*)d_in[4];
    const float* b0b = (const float*)d_in[5];
    const float* W1a = (const float*)d_in[6];
    const float* b1a = (const float*)d_in[7];
    const float* W1b = (const float*)d_in[8];
    const float* b1b = (const float*)d_in[9];

    float* out = (float*)d_out;
    long long simN = (long long)M_DIM * N_DIM;
    long long extra = (long long)out_size - simN;

    float* idx_out = nullptr;
    float* sim = out;
    if (extra >= 2 * TOPK) {  // tuple layout: [indices (TOPK*2)] [sim (M*N)]
        idx_out = out;
        sim = out + extra;
    }

    cudaFuncSetAttribute(gemm_mma_kernel,
                         cudaFuncAttributeMaxDynamicSharedMemorySize, GSMEM_BYTES);

    reset_kernel<<<1, 1024>>>();
    mlp_kernel<<<512, 256>>>(desc0, desc1, W0a, b0a, W0b, b0b, W1a, b1a, W1b, b1b);
    gemm_mma_kernel<<<dim3(N_DIM / 128, M_DIM / 128), 256, GSMEM_BYTES>>>(sim);

    if (idx_out) {
        hist_kernel<<<128, 256>>>();
        cut_kernel<<<1, 512>>>();
        cand_kernel<<<128, 256>>>();
        refine_kernel<<<128, 256>>>();
        rank_kernel<<<64, 256>>>(idx_out);
    }
}

// round 11
// speedup vs baseline: 9.7886x; 9.7886x over previous
#include <cuda_runtime.h>
#include <cuda_fp16.h>
#include <cstdint>

#define M_DIM 8192
#define N_DIM 8192
#define IN_DIM 128
#define HID 256
#define TOPK 512
#define WINBINS 512
#define CAND_CAP (1 << 16)
#define NTILES (128 * 256)   // 64x32 warp tiles

// ---------------- device scratch (no allocations allowed) ----------------
__device__ __half g_md0h[M_DIM * HID];
__device__ __half g_md0l[M_DIM * HID];
__device__ __half g_md1h[N_DIM * HID];
__device__ __half g_md1l[N_DIM * HID];
__device__ float g_md0f[M_DIM * HID];
__device__ float g_md1f[N_DIM * HID];
__device__ unsigned short g_key16[(size_t)M_DIM * N_DIM];  // compact sort keys
__device__ unsigned short g_tilemax[NTILES];               // per 64x32 tile key max
__device__ unsigned int g_hist[WINBINS];
__device__ unsigned int g_maxkey;
__device__ unsigned int g_cutabs;   // 16-bit key threshold
__device__ unsigned int g_cand_count;
__device__ unsigned int g_cand_idx[CAND_CAP];
__device__ double g_cand_ref[CAND_CAP];

__device__ __forceinline__ unsigned int fkey(float v) {
    unsigned int u = __float_as_uint(v);
    return (u & 0x80000000u) ? ~u : (u | 0x80000000u);
}

// ---------------- reset ----------------
__global__ void reset_kernel() {
    int t = threadIdx.x;
    if (t < WINBINS) g_hist[t] = 0;
    if (t == 0) { g_maxkey = 0; g_cand_count = 0; }
}

// ---------------- MLP (both descriptors in one grid) ----------------
__global__ void __launch_bounds__(256) mlp_kernel(
    const float* __restrict__ x0, const float* __restrict__ x1,
    const float* __restrict__ W0a, const float* __restrict__ b0a,
    const float* __restrict__ W0b, const float* __restrict__ b0b,
    const float* __restrict__ W1a, const float* __restrict__ b1a,
    const float* __restrict__ W1b, const float* __restrict__ b1b)
{
    __shared__ float xs[32 * IN_DIM];
    __shared__ float hs[32 * HID];
    int which = (blockIdx.x >= 256) ? 1 : 0;
    int blk = blockIdx.x & 255;
    const float* x = which ? x1 : x0;
    const float* Wa = which ? W1a : W0a;
    const float* ba = which ? b1a : b0a;
    const float* Wb = which ? W1b : W0b;
    const float* bb = which ? b1b : b0b;
    __half* outh = which ? g_md1h : g_md0h;
    __half* outl = which ? g_md1l : g_md0l;
    float* outf = which ? g_md1f : g_md0f;

    int tid = threadIdx.x;
    const float* xb = x + (size_t)blk * 32 * IN_DIM;

    {
        const float4* src = (const float4*)xb;
        float4* dst = (float4*)xs;
        for (int i = tid; i < 32 * IN_DIM / 4; i += 256) dst[i] = src[i];
    }
    __syncthreads();

    float acc[32];
    float bav = ba[tid];
#pragma unroll
    for (int r = 0; r < 32; r++) acc[r] = bav;

    const float4* xs4 = (const float4*)xs;
    for (int k = 0; k < IN_DIM; k += 4) {
        float w0 = Wa[(k + 0) * HID + tid];
        float w1 = Wa[(k + 1) * HID + tid];
        float w2 = Wa[(k + 2) * HID + tid];
        float w3 = Wa[(k + 3) * HID + tid];
#pragma unroll
        for (int r = 0; r < 32; r++) {
            float4 xv = xs4[r * (IN_DIM / 4) + (k >> 2)];
            acc[r] += xv.x * w0; acc[r] += xv.y * w1;
            acc[r] += xv.z * w2; acc[r] += xv.w * w3;
        }
    }
#pragma unroll
    for (int r = 0; r < 32; r++) hs[r * HID + tid] = fmaxf(acc[r], 0.0f);
    __syncthreads();

    float bbv = bb[tid];
#pragma unroll
    for (int r = 0; r < 32; r++) acc[r] = bbv;

    const float4* hs4 = (const float4*)hs;
    for (int k = 0; k < HID; k += 4) {
        float w0 = Wb[(k + 0) * HID + tid];
        float w1 = Wb[(k + 1) * HID + tid];
        float w2 = Wb[(k + 2) * HID + tid];
        float w3 = Wb[(k + 3) * HID + tid];
#pragma unroll
        for (int r = 0; r < 32; r++) {
            float4 hv = hs4[r * (HID / 4) + (k >> 2)];
            acc[r] += hv.x * w0; acc[r] += hv.y * w1;
            acc[r] += hv.z * w2; acc[r] += hv.w * w3;
        }
    }
#pragma unroll
    for (int r = 0; r < 32; r++) {
        float v = acc[r];
        __half hi = __float2half_rn(v);
        __half lo = __float2half_rn(v - __half2float(hi));
        size_t o = ((size_t)blk * 32 + r) * HID + tid;
        outh[o] = hi;
        outl[o] = lo;
        outf[o] = v;
    }
}

// ---------------- fp16 3-term NT GEMM, BK=32, 2 CTAs/SM, key16 + tilemax side outputs ----------------
#define BK 32
#define PITCH 40                       // halves per smem row (80B: 20-word rows -> 4-bank skew)
#define ROWB (PITCH * 2)               // 80 bytes
#define PLANE_BYTES (128 * ROWB)       // 10240
#define BUF_BYTES (4 * PLANE_BYTES)    // 40960 (Ah, Al, Bh, Bl)
#define GSMEM_BYTES (2 * BUF_BYTES)    // 81920 -> 2 CTAs/SM

__device__ __forceinline__ uint32_t smem_u32(const void* p) {
    uint32_t a;
    asm("{ .reg .u64 t; cvta.to.shared.u64 t, %1; cvt.u32.u64 %0, t; }" : "=r"(a) : "l"(p));
    return a;
}
__device__ __forceinline__ void cp16(uint32_t dst, const void* src) {
    asm volatile("cp.async.cg.shared.global [%0], [%1], 16;" :: "r"(dst), "l"(src) : "memory");
}
__device__ __forceinline__ void cp_commit() { asm volatile("cp.async.commit_group;" ::: "memory"); }
template <int N>
__device__ __forceinline__ void cp_wait() { asm volatile("cp.async.wait_group %0;" :: "n"(N) : "memory"); }

__device__ __forceinline__ void ldsm_x4(uint32_t& r0, uint32_t& r1, uint32_t& r2, uint32_t& r3,
                                        uint32_t addr) {
    asm volatile("ldmatrix.sync.aligned.m8n8.x4.shared.b16 {%0,%1,%2,%3}, [%4];"
                 : "=r"(r0), "=r"(r1), "=r"(r2), "=r"(r3) : "r"(addr));
}
__device__ __forceinline__ void ldsm_x2(uint32_t& r0, uint32_t& r1, uint32_t addr) {
    asm volatile("ldmatrix.sync.aligned.m8n8.x2.shared.b16 {%0,%1}, [%2];"
                 : "=r"(r0), "=r"(r1) : "r"(addr));
}

__device__ __forceinline__ void mma16816(float* d, uint32_t a0, uint32_t a1, uint32_t a2,
                                         uint32_t a3, uint32_t b0, uint32_t b1) {
    asm volatile(
        "mma.sync.aligned.m16n8k16.row.col.f32.f16.f16.f32 "
        "{%0,%1,%2,%3}, {%4,%5,%6,%7}, {%8,%9}, {%0,%1,%2,%3};"
        : "+f"(d[0]), "+f"(d[1]), "+f"(d[2]), "+f"(d[3])
        : "r"(a0), "r"(a1), "r"(a2), "r"(a3), "r"(b0), "r"(b1));
}

__global__ void __launch_bounds__(256, 2) gemm_mma_kernel(float* __restrict__ C) {
    extern __shared__ char smem[];
    uint32_t sb = smem_u32(smem);

    int tid = threadIdx.x;
    int wid = tid >> 5;
    int lane = tid & 31;
    int gid = lane >> 2;
    int tig = lane & 3;
    int m0 = blockIdx.y * 128;
    int n0 = blockIdx.x * 128;
    int wm = (wid >> 2) * 64;
    int wn = (wid & 3) * 32;

    float acc[4][4][4];
#pragma unroll
    for (int i = 0; i < 4; i++)
#pragma unroll
        for (int j = 0; j < 4; j++)
#pragma unroll
            for (int k = 0; k < 4; k++) acc[i][j][k] = 0.0f;

    const __half* planes_g[4] = {g_md0h, g_md0l, g_md1h, g_md1l};

    auto issue_chunk = [&](int kc, int buf) {
        uint32_t base = sb + buf * BUF_BYTES;
#pragma unroll
        for (int p = 0; p < 4; p++) {
            const __half* gp = planes_g[p];
            int row0 = (p < 2) ? m0 : n0;
#pragma unroll
            for (int j = 0; j < 2; j++) {
                int chunk = tid * 2 + j;       // 0..511
                int row = chunk >> 2;
                int seg = chunk & 3;           // 16B segment within 64B row
                uint32_t dst = base + p * PLANE_BYTES + row * ROWB + seg * 16;
                const void* src = gp + (size_t)(row0 + row) * HID + kc * BK + seg * 8;
                cp16(dst, src);
            }
        }
        cp_commit();
    };

    int a_rowadd = (lane & 7) + ((lane >> 3) & 1) * 8;
    int a_seg = (lane >> 4) * 16;
    int b_lane = lane & 15;
    int b_rowadd = b_lane & 7;
    int b_seg = ((b_lane >> 3) & 1) * 16;

    issue_chunk(0, 0);

    const int NCH = HID / BK;  // 8
    for (int kc = 0; kc < NCH; kc++) {
        int buf = kc & 1;
        if (kc + 1 < NCH) {
            issue_chunk(kc + 1, (kc + 1) & 1);
            cp_wait<1>();
        } else {
            cp_wait<0>();
        }
        __syncthreads();

        uint32_t bufb = sb + buf * BUF_BYTES;
        uint32_t pAh = bufb + 0 * PLANE_BYTES;
        uint32_t pAl = bufb + 1 * PLANE_BYTES;
        uint32_t pBh = bufb + 2 * PLANE_BYTES;
        uint32_t pBl = bufb + 3 * PLANE_BYTES;

#pragma unroll
        for (int ks = 0; ks < BK / 16; ks++) {
            uint32_t kso = ks * 32;
            uint32_t ah[4][4], al[4][4], bh[4][2], bl[4][2];
#pragma unroll
            for (int mt = 0; mt < 4; mt++) {
                uint32_t ro = (uint32_t)(wm + mt * 16 + a_rowadd) * ROWB + kso + a_seg;
                ldsm_x4(ah[mt][0], ah[mt][1], ah[mt][2], ah[mt][3], pAh + ro);
                ldsm_x4(al[mt][0], al[mt][1], al[mt][2], al[mt][3], pAl + ro);
            }
#pragma unroll
            for (int nt = 0; nt < 4; nt++) {
                uint32_t ro = (uint32_t)(wn + nt * 8 + b_rowadd) * ROWB + kso + b_seg;
                ldsm_x2(bh[nt][0], bh[nt][1], pBh + ro);
                ldsm_x2(bl[nt][0], bl[nt][1], pBl + ro);
            }
#pragma unroll
            for (int mt = 0; mt < 4; mt++)
#pragma unroll
                for (int nt = 0; nt < 4; nt++) {
                    mma16816(acc[mt][nt], ah[mt][0], ah[mt][1], ah[mt][2], ah[mt][3],
                             bh[nt][0], bh[nt][1]);
                    mma16816(acc[mt][nt], ah[mt][0], ah[mt][1], ah[mt][2], ah[mt][3],
                             bl[nt][0], bl[nt][1]);
                    mma16816(acc[mt][nt], al[mt][0], al[mt][1], al[mt][2], al[mt][3],
                             bh[nt][0], bh[nt][1]);
                }
        }
        __syncthreads();
    }

    // epilogue: store C + packed key16 plane + tile max + fused global max
    unsigned int mymax = 0;
#pragma unroll
    for (int mt = 0; mt < 4; mt++) {
        int r0 = m0 + wm + mt * 16 + gid;
#pragma unroll
        for (int nt = 0; nt < 4; nt++) {
            int col = n0 + wn + nt * 8 + 2 * tig;
            size_t o0 = (size_t)r0 * N_DIM + col;
            size_t o1 = (size_t)(r0 + 8) * N_DIM + col;
            *(float2*)(C + o0) = make_float2(acc[mt][nt][0], acc[mt][nt][1]);
            *(float2*)(C + o1) = make_float2(acc[mt][nt][2], acc[mt][nt][3]);
            unsigned int k0 = fkey(acc[mt][nt][0]), k1 = fkey(acc[mt][nt][1]);
            unsigned int k2 = fkey(acc[mt][nt][2]), k3 = fkey(acc[mt][nt][3]);
            *(uint32_t*)(g_key16 + o0) = (k0 >> 16) | (k1 & 0xffff0000u);
            *(uint32_t*)(g_key16 + o1) = (k2 >> 16) | (k3 & 0xffff0000u);
            mymax = max(max(mymax, max(k0, k1)), max(k2, k3));
        }
    }
#pragma unroll
    for (int s = 16; s > 0; s >>= 1)
        mymax = max(mymax, __shfl_xor_sync(0xffffffffu, mymax, s));

    // warp tile max -> g_tilemax (tile = 64 rows x 32 cols)
    if (lane == 0) {
        int mt = blockIdx.y * 2 + (wid >> 2);   // 0..127
        int nt = blockIdx.x * 4 + (wid & 3);    // 0..255
        g_tilemax[mt * 256 + nt] = (unsigned short)(mymax >> 16);
    }

    __shared__ unsigned int wmax[8];
    if (lane == 0) wmax[wid] = mymax;
    __syncthreads();
    if (tid == 0) {
        unsigned int m = wmax[0];
#pragma unroll
        for (int i = 1; i < 8; i++) m = max(m, wmax[i]);
        atomicMax(&g_maxkey, m);
    }
}

// ---------------- streaming windowed histogram (R9-proven: smem-aggregated, SIMD fast-skip) ----------------
__global__ void hist_kernel(int n8) {
    __shared__ unsigned int sh[WINBINS];
    for (int i = threadIdx.x; i < WINBINS; i += blockDim.x) sh[i] = 0;
    __syncthreads();
    unsigned int maxk16 = g_maxkey >> 16;
    unsigned int wcut = maxk16 - (WINBINS - 1);
    unsigned int wc2 = (wcut << 16) | wcut;
    const uint4* k8 = (const uint4*)g_key16;
    int stride = gridDim.x * blockDim.x;
    for (int i = blockIdx.x * blockDim.x + threadIdx.x; i < n8; i += stride) {
        uint4 v = k8[i];
        // packed u16 >= test: one vcmp per word, branch almost never taken
        unsigned int any = __vcmpgeu2(v.x, wc2) | __vcmpgeu2(v.y, wc2)
                         | __vcmpgeu2(v.z, wc2) | __vcmpgeu2(v.w, wc2);
        if (any) {
            unsigned int w[4] = {v.x, v.y, v.z, v.w};
#pragma unroll
            for (int j = 0; j < 4; j++) {
                unsigned int rlo = maxk16 - (w[j] & 0xffffu);
                unsigned int rhi = maxk16 - (w[j] >> 16);
                if (rlo < WINBINS) atomicAdd(&sh[rlo], 1u);
                if (rhi < WINBINS) atomicAdd(&sh[rhi], 1u);
            }
        }
    }
    __syncthreads();
    for (int i = threadIdx.x; i < WINBINS; i += blockDim.x)
        if (sh[i]) atomicAdd(&g_hist[i], sh[i]);
}

// ---------------- find cut: parallel prefix scan over 512 bins, +1 bin margin ----------------
__global__ void __launch_bounds__(512) cut_kernel() {
    __shared__ unsigned int pfx[WINBINS];
    int t = threadIdx.x;
    pfx[t] = g_hist[t];
    __syncthreads();
    for (int off = 1; off < WINBINS; off <<= 1) {
        unsigned int v = (t >= off) ? pfx[t - off] : 0u;
        __syncthreads();
        pfx[t] += v;
        __syncthreads();
    }
    unsigned int maxk16 = g_maxkey >> 16;
    if (pfx[t] >= TOPK && (t == 0 || pfx[t - 1] < TOPK))
        g_cutabs = maxk16 - (unsigned int)(t + 1);   // +1 bin margin
    if (t == WINBINS - 1 && pfx[t] < TOPK)
        g_cutabs = maxk16 - (unsigned int)WINBINS;
}

// ---------------- tile-pruned candidate collection (cutabs prune is tight AND exact) ----------------
__global__ void cand_kernel() {
    unsigned int cutabs = g_cutabs;
    int lane = threadIdx.x & 31;
    int warp = (int)((blockIdx.x * blockDim.x + threadIdx.x) >> 5);
    int nwarp = (int)((gridDim.x * blockDim.x) >> 5);
    int r = lane >> 2, c4 = lane & 3;
    for (int base = warp * 32; base < NTILES; base += nwarp * 32) {
        unsigned int tm = g_tilemax[base + lane];
        unsigned int mask = __ballot_sync(0xffffffffu, tm >= cutabs);
        while (mask) {
            int b = __ffs(mask) - 1;
            mask &= mask - 1;
            int tt = base + b;
            int m0 = (tt >> 8) * 64, n0 = (tt & 255) * 32;
            for (int rr = 0; rr < 64; rr += 8) {
                size_t rowoff = (size_t)(m0 + rr + r) * N_DIM + n0 + c4 * 8;
                const uint4* p = (const uint4*)(g_key16 + rowoff);
                uint4 v = *p;
                unsigned int w[4] = {v.x, v.y, v.z, v.w};
#pragma unroll
                for (int j = 0; j < 4; j++) {
                    if ((w[j] & 0xffffu) >= cutabs) {
                        unsigned int pos = atomicAdd(&g_cand_count, 1u);
                        if (pos < CAND_CAP) g_cand_idx[pos] = (unsigned int)(rowoff + 2 * j);
                    }
                    if ((w[j] >> 16) >= cutabs) {
                        unsigned int pos = atomicAdd(&g_cand_count, 1u);
                        if (pos < CAND_CAP) g_cand_idx[pos] = (unsigned int)(rowoff + 2 * j + 1);
                    }
                }
            }
        }
    }
}

// ---------------- refine: exact fp64 dot per candidate ----------------
__global__ void refine_kernel() {
    unsigned int count = g_cand_count;
    if (count > CAND_CAP) count = CAND_CAP;
    unsigned int warp = (blockIdx.x * blockDim.x + threadIdx.x) >> 5;
    unsigned int nwarp = (gridDim.x * blockDim.x) >> 5;
    int lane = threadIdx.x & 31;
    for (unsigned int c = warp; c < count; c += nwarp) {
        unsigned int idx = g_cand_idx[c];
        const float* a = g_md0f + (size_t)(idx >> 13) * HID;
        const float* b = g_md1f + (size_t)(idx & 8191u) * HID;
        double s = 0.0;
#pragma unroll
        for (int k = 0; k < HID / 32; k++)
            s += (double)a[k * 32 + lane] * (double)b[k * 32 + lane];
#pragma unroll
        for (int o = 16; o > 0; o >>= 1)
            s += __shfl_xor_sync(0xffffffffu, s, o);
        if (lane == 0) g_cand_ref[c] = s;
    }
}

// ---------------- rank-select on refined values (deterministic) ----------------
__global__ void __launch_bounds__(256) rank_kernel(float* __restrict__ idx_out) {
    unsigned int count = g_cand_count;
    if (count > CAND_CAP) count = CAND_CAP;
    unsigned int stride = gridDim.x * blockDim.x;
    for (unsigned int i = blockIdx.x * blockDim.x + threadIdx.x; i < count; i += stride) {
        double vi = g_cand_ref[i];
        unsigned int ii = g_cand_idx[i];
        unsigned int rank = 0;
        for (unsigned int j = 0; j < count; j++) {
            double vj = g_cand_ref[j];
            unsigned int ij = g_cand_idx[j];
            if (vj > vi || (vj == vi && ij < ii)) rank++;
        }
        if (rank < TOPK) {
            idx_out[rank * 2 + 0] = (float)(ii >> 13);
            idx_out[rank * 2 + 1] = (float)(ii & 8191u);
        }
    }
}

// ---------------- launch ----------------
extern "C" void kernel_launch(void* const* d_in, const int* in_sizes, int n_in,
                              void* d_out, int out_size) {
    const float* desc0 = (const float*)d_in[0];
    const float* desc1 = (const float*)d_in[1];
    const float* W0a = (const float*)d_in[2];
    const float* b0a = (const float*)d_in[3];
    const float* W0b = (const float*)d_in[4];
    const float* b0b = (const float*)d_in[5];
    const float* W1a = (const float*)d_in[6];
    const float* b1a = (const float*)d_in[7];
    const float* W1b = (const float*)d_in[8];
    const float* b1b = (const float*)d_in[9];

    float* out = (float*)d_out;
    long long simN = (long long)M_DIM * N_DIM;
    long long extra = (long long)out_size - simN;

    float* idx_out = nullptr;
    float* sim = out;
    if (extra >= 2 * TOPK) {  // tuple layout: [indices (TOPK*2)] [sim (M*N)]
        idx_out = out;
        sim = out + extra;
    }

    cudaFuncSetAttribute(gemm_mma_kernel,
                         cudaFuncAttributeMaxDynamicSharedMemorySize, GSMEM_BYTES);

    reset_kernel<<<1, 1024>>>();
    mlp_kernel<<<512, 256>>>(desc0, desc1, W0a, b0a, W0b, b0b, W1a, b1a, W1b, b1b);
    gemm_mma_kernel<<<dim3(N_DIM / 128, M_DIM / 128), 256, GSMEM_BYTES>>>(sim);

    if (idx_out) {
        int n8 = (int)(simN / 8);
        hist_kernel<<<1184, 256>>>(n8);
        cut_kernel<<<1, 512>>>();
        cand_kernel<<<128, 256>>>();
        refine_kernel<<<128, 256>>>();
        rank_kernel<<<64, 256>>>(idx_out);
    }
}

// round 12
// speedup vs baseline: 10.0586x; 1.0276x over previous
#include <cuda_runtime.h>
#include <cuda_fp16.h>
#include <cstdint>

#define M_DIM 8192
#define N_DIM 8192
#define IN_DIM 128
#define HID 256
#define TOPK 512
#define WINBINS 512
#define CAND_CAP (1 << 16)
#define NTILES (128 * 256)   // 64x32 warp tiles

// ---------------- device scratch (no allocations allowed) ----------------
__device__ __half g_md0h[M_DIM * HID];
__device__ __half g_md0l[M_DIM * HID];
__device__ __half g_md1h[N_DIM * HID];
__device__ __half g_md1l[N_DIM * HID];
__device__ float g_md0f[M_DIM * HID];
__device__ float g_md1f[N_DIM * HID];
__device__ unsigned short g_key16[(size_t)M_DIM * N_DIM];  // compact sort keys
__device__ unsigned short g_tilemax[NTILES];               // per 64x32 tile key max
__device__ unsigned int g_hist[WINBINS];
__device__ unsigned int g_maxkey;
__device__ unsigned int g_prelim;   // preliminary (provably-low) cut from tile maxima
__device__ unsigned int g_cutabs;   // final 16-bit key threshold
__device__ unsigned int g_cand_count;
__device__ unsigned int g_cand_idx[CAND_CAP];
__device__ double g_cand_ref[CAND_CAP];

__device__ __forceinline__ unsigned int fkey(float v) {
    unsigned int u = __float_as_uint(v);
    return (u & 0x80000000u) ? ~u : (u | 0x80000000u);
}

// ---------------- reset ----------------
__global__ void reset_kernel() {
    int t = threadIdx.x;
    if (t < WINBINS) g_hist[t] = 0;
    if (t == 0) { g_maxkey = 0; g_cand_count = 0; }
}

// ---------------- MLP (both descriptors in one grid) ----------------
__global__ void __launch_bounds__(256) mlp_kernel(
    const float* __restrict__ x0, const float* __restrict__ x1,
    const float* __restrict__ W0a, const float* __restrict__ b0a,
    const float* __restrict__ W0b, const float* __restrict__ b0b,
    const float* __restrict__ W1a, const float* __restrict__ b1a,
    const float* __restrict__ W1b, const float* __restrict__ b1b)
{
    __shared__ float xs[32 * IN_DIM];
    __shared__ float hs[32 * HID];
    int which = (blockIdx.x >= 256) ? 1 : 0;
    int blk = blockIdx.x & 255;
    const float* x = which ? x1 : x0;
    const float* Wa = which ? W1a : W0a;
    const float* ba = which ? b1a : b0a;
    const float* Wb = which ? W1b : W0b;
    const float* bb = which ? b1b : b0b;
    __half* outh = which ? g_md1h : g_md0h;
    __half* outl = which ? g_md1l : g_md0l;
    float* outf = which ? g_md1f : g_md0f;

    int tid = threadIdx.x;
    const float* xb = x + (size_t)blk * 32 * IN_DIM;

    {
        const float4* src = (const float4*)xb;
        float4* dst = (float4*)xs;
        for (int i = tid; i < 32 * IN_DIM / 4; i += 256) dst[i] = src[i];
    }
    __syncthreads();

    float acc[32];
    float bav = ba[tid];
#pragma unroll
    for (int r = 0; r < 32; r++) acc[r] = bav;

    const float4* xs4 = (const float4*)xs;
    for (int k = 0; k < IN_DIM; k += 4) {
        float w0 = Wa[(k + 0) * HID + tid];
        float w1 = Wa[(k + 1) * HID + tid];
        float w2 = Wa[(k + 2) * HID + tid];
        float w3 = Wa[(k + 3) * HID + tid];
#pragma unroll
        for (int r = 0; r < 32; r++) {
            float4 xv = xs4[r * (IN_DIM / 4) + (k >> 2)];
            acc[r] += xv.x * w0; acc[r] += xv.y * w1;
            acc[r] += xv.z * w2; acc[r] += xv.w * w3;
        }
    }
#pragma unroll
    for (int r = 0; r < 32; r++) hs[r * HID + tid] = fmaxf(acc[r], 0.0f);
    __syncthreads();

    float bbv = bb[tid];
#pragma unroll
    for (int r = 0; r < 32; r++) acc[r] = bbv;

    const float4* hs4 = (const float4*)hs;
    for (int k = 0; k < HID; k += 4) {
        float w0 = Wb[(k + 0) * HID + tid];
        float w1 = Wb[(k + 1) * HID + tid];
        float w2 = Wb[(k + 2) * HID + tid];
        float w3 = Wb[(k + 3) * HID + tid];
#pragma unroll
        for (int r = 0; r < 32; r++) {
            float4 hv = hs4[r * (HID / 4) + (k >> 2)];
            acc[r] += hv.x * w0; acc[r] += hv.y * w1;
            acc[r] += hv.z * w2; acc[r] += hv.w * w3;
        }
    }
#pragma unroll
    for (int r = 0; r < 32; r++) {
        float v = acc[r];
        __half hi = __float2half_rn(v);
        __half lo = __float2half_rn(v - __half2float(hi));
        size_t o = ((size_t)blk * 32 + r) * HID + tid;
        outh[o] = hi;
        outl[o] = lo;
        outf[o] = v;
    }
}

// ---------------- fp16 3-term NT GEMM, BK=32, 2 CTAs/SM, key16 + tilemax side outputs ----------------
#define BK 32
#define PITCH 40                       // halves per smem row (80B: 20-word rows -> 4-bank skew)
#define ROWB (PITCH * 2)               // 80 bytes
#define PLANE_BYTES (128 * ROWB)       // 10240
#define BUF_BYTES (4 * PLANE_BYTES)    // 40960 (Ah, Al, Bh, Bl)
#define GSMEM_BYTES (2 * BUF_BYTES)    // 81920 -> 2 CTAs/SM

__device__ __forceinline__ uint32_t smem_u32(const void* p) {
    uint32_t a;
    asm("{ .reg .u64 t; cvta.to.shared.u64 t, %1; cvt.u32.u64 %0, t; }" : "=r"(a) : "l"(p));
    return a;
}
__device__ __forceinline__ void cp16(uint32_t dst, const void* src) {
    asm volatile("cp.async.cg.shared.global [%0], [%1], 16;" :: "r"(dst), "l"(src) : "memory");
}
__device__ __forceinline__ void cp_commit() { asm volatile("cp.async.commit_group;" ::: "memory"); }
template <int N>
__device__ __forceinline__ void cp_wait() { asm volatile("cp.async.wait_group %0;" :: "n"(N) : "memory"); }

__device__ __forceinline__ void ldsm_x4(uint32_t& r0, uint32_t& r1, uint32_t& r2, uint32_t& r3,
                                        uint32_t addr) {
    asm volatile("ldmatrix.sync.aligned.m8n8.x4.shared.b16 {%0,%1,%2,%3}, [%4];"
                 : "=r"(r0), "=r"(r1), "=r"(r2), "=r"(r3) : "r"(addr));
}
__device__ __forceinline__ void ldsm_x2(uint32_t& r0, uint32_t& r1, uint32_t addr) {
    asm volatile("ldmatrix.sync.aligned.m8n8.x2.shared.b16 {%0,%1}, [%2];"
                 : "=r"(r0), "=r"(r1) : "r"(addr));
}

__device__ __forceinline__ void mma16816(float* d, uint32_t a0, uint32_t a1, uint32_t a2,
                                         uint32_t a3, uint32_t b0, uint32_t b1) {
    asm volatile(
        "mma.sync.aligned.m16n8k16.row.col.f32.f16.f16.f32 "
        "{%0,%1,%2,%3}, {%4,%5,%6,%7}, {%8,%9}, {%0,%1,%2,%3};"
        : "+f"(d[0]), "+f"(d[1]), "+f"(d[2]), "+f"(d[3])
        : "r"(a0), "r"(a1), "r"(a2), "r"(a3), "r"(b0), "r"(b1));
}

__global__ void __launch_bounds__(256, 2) gemm_mma_kernel(float* __restrict__ C) {
    extern __shared__ char smem[];
    uint32_t sb = smem_u32(smem);

    int tid = threadIdx.x;
    int wid = tid >> 5;
    int lane = tid & 31;
    int gid = lane >> 2;
    int tig = lane & 3;
    int m0 = blockIdx.y * 128;
    int n0 = blockIdx.x * 128;
    int wm = (wid >> 2) * 64;
    int wn = (wid & 3) * 32;

    float acc[4][4][4];
#pragma unroll
    for (int i = 0; i < 4; i++)
#pragma unroll
        for (int j = 0; j < 4; j++)
#pragma unroll
            for (int k = 0; k < 4; k++) acc[i][j][k] = 0.0f;

    const __half* planes_g[4] = {g_md0h, g_md0l, g_md1h, g_md1l};

    auto issue_chunk = [&](int kc, int buf) {
        uint32_t base = sb + buf * BUF_BYTES;
#pragma unroll
        for (int p = 0; p < 4; p++) {
            const __half* gp = planes_g[p];
            int row0 = (p < 2) ? m0 : n0;
#pragma unroll
            for (int j = 0; j < 2; j++) {
                int chunk = tid * 2 + j;       // 0..511
                int row = chunk >> 2;
                int seg = chunk & 3;           // 16B segment within 64B row
                uint32_t dst = base + p * PLANE_BYTES + row * ROWB + seg * 16;
                const void* src = gp + (size_t)(row0 + row) * HID + kc * BK + seg * 8;
                cp16(dst, src);
            }
        }
        cp_commit();
    };

    int a_rowadd = (lane & 7) + ((lane >> 3) & 1) * 8;
    int a_seg = (lane >> 4) * 16;
    int b_lane = lane & 15;
    int b_rowadd = b_lane & 7;
    int b_seg = ((b_lane >> 3) & 1) * 16;

    issue_chunk(0, 0);

    const int NCH = HID / BK;  // 8
    for (int kc = 0; kc < NCH; kc++) {
        int buf = kc & 1;
        if (kc + 1 < NCH) {
            issue_chunk(kc + 1, (kc + 1) & 1);
            cp_wait<1>();
        } else {
            cp_wait<0>();
        }
        __syncthreads();

        uint32_t bufb = sb + buf * BUF_BYTES;
        uint32_t pAh = bufb + 0 * PLANE_BYTES;
        uint32_t pAl = bufb + 1 * PLANE_BYTES;
        uint32_t pBh = bufb + 2 * PLANE_BYTES;
        uint32_t pBl = bufb + 3 * PLANE_BYTES;

#pragma unroll
        for (int ks = 0; ks < BK / 16; ks++) {
            uint32_t kso = ks * 32;
            uint32_t ah[4][4], al[4][4], bh[4][2], bl[4][2];
#pragma unroll
            for (int mt = 0; mt < 4; mt++) {
                uint32_t ro = (uint32_t)(wm + mt * 16 + a_rowadd) * ROWB + kso + a_seg;
                ldsm_x4(ah[mt][0], ah[mt][1], ah[mt][2], ah[mt][3], pAh + ro);
                ldsm_x4(al[mt][0], al[mt][1], al[mt][2], al[mt][3], pAl + ro);
            }
#pragma unroll
            for (int nt = 0; nt < 4; nt++) {
                uint32_t ro = (uint32_t)(wn + nt * 8 + b_rowadd) * ROWB + kso + b_seg;
                ldsm_x2(bh[nt][0], bh[nt][1], pBh + ro);
                ldsm_x2(bl[nt][0], bl[nt][1], pBl + ro);
            }
#pragma unroll
            for (int mt = 0; mt < 4; mt++)
#pragma unroll
                for (int nt = 0; nt < 4; nt++) {
                    mma16816(acc[mt][nt], ah[mt][0], ah[mt][1], ah[mt][2], ah[mt][3],
                             bh[nt][0], bh[nt][1]);
                    mma16816(acc[mt][nt], ah[mt][0], ah[mt][1], ah[mt][2], ah[mt][3],
                             bl[nt][0], bl[nt][1]);
                    mma16816(acc[mt][nt], al[mt][0], al[mt][1], al[mt][2], al[mt][3],
                             bh[nt][0], bh[nt][1]);
                }
        }
        __syncthreads();
    }

    // epilogue: store C + packed key16 plane + tile max + fused global max
    unsigned int mymax = 0;
#pragma unroll
    for (int mt = 0; mt < 4; mt++) {
        int r0 = m0 + wm + mt * 16 + gid;
#pragma unroll
        for (int nt = 0; nt < 4; nt++) {
            int col = n0 + wn + nt * 8 + 2 * tig;
            size_t o0 = (size_t)r0 * N_DIM + col;
            size_t o1 = (size_t)(r0 + 8) * N_DIM + col;
            *(float2*)(C + o0) = make_float2(acc[mt][nt][0], acc[mt][nt][1]);
            *(float2*)(C + o1) = make_float2(acc[mt][nt][2], acc[mt][nt][3]);
            unsigned int k0 = fkey(acc[mt][nt][0]), k1 = fkey(acc[mt][nt][1]);
            unsigned int k2 = fkey(acc[mt][nt][2]), k3 = fkey(acc[mt][nt][3]);
            *(uint32_t*)(g_key16 + o0) = (k0 >> 16) | (k1 & 0xffff0000u);
            *(uint32_t*)(g_key16 + o1) = (k2 >> 16) | (k3 & 0xffff0000u);
            mymax = max(max(mymax, max(k0, k1)), max(k2, k3));
        }
    }
#pragma unroll
    for (int s = 16; s > 0; s >>= 1)
        mymax = max(mymax, __shfl_xor_sync(0xffffffffu, mymax, s));

    // warp tile max -> g_tilemax (tile = 64 rows x 32 cols)
    if (lane == 0) {
        int mt = blockIdx.y * 2 + (wid >> 2);   // 0..127
        int nt = blockIdx.x * 4 + (wid & 3);    // 0..255
        g_tilemax[mt * 256 + nt] = (unsigned short)(mymax >> 16);
    }

    __shared__ unsigned int wmax[8];
    if (lane == 0) wmax[wid] = mymax;
    __syncthreads();
    if (tid == 0) {
        unsigned int m = wmax[0];
#pragma unroll
        for (int i = 1; i < 8; i++) m = max(m, wmax[i]);
        atomicMax(&g_maxkey, m);
    }
}

// ---------------- tilesel: p = threshold with >= TOPK tile maxima above (provably <= true cut) ----------------
__global__ void __launch_bounds__(512) tilesel_kernel() {
    __shared__ unsigned int h[WINBINS];
    __shared__ unsigned int pfx[WINBINS];
    int t = threadIdx.x;
    h[t] = 0;
    __syncthreads();
    unsigned int maxk16 = g_maxkey >> 16;
    for (int i = t; i < NTILES; i += 512) {
        unsigned int rel = maxk16 - (unsigned int)g_tilemax[i];
        if (rel < WINBINS) atomicAdd(&h[rel], 1u);
    }
    __syncthreads();
    pfx[t] = h[t];
    __syncthreads();
    for (int off = 1; off < WINBINS; off <<= 1) {
        unsigned int v = (t >= off) ? pfx[t - off] : 0u;
        __syncthreads();
        pfx[t] += v;
        __syncthreads();
    }
    // smallest t with >= TOPK tiles at rel <= t  ->  p = maxk16 - t
    if (pfx[t] >= TOPK && (t == 0 || pfx[t - 1] < TOPK))
        g_prelim = maxk16 - (unsigned int)t;
    if (t == WINBINS - 1 && pfx[t] < TOPK)
        g_prelim = maxk16 - (unsigned int)(WINBINS - 1);  // <TOPK tiles in window: scan them all
}

// ---------------- restricted windowed histogram: only tiles with max >= p (exact for bins >= p) ----------------
__global__ void hist_kernel() {
    __shared__ unsigned int sh[WINBINS];
    for (int i = threadIdx.x; i < WINBINS; i += blockDim.x) sh[i] = 0;
    __syncthreads();
    unsigned int maxk16 = g_maxkey >> 16;
    unsigned int p = g_prelim;
    int lane = threadIdx.x & 31;
    int warp = (int)((blockIdx.x * blockDim.x + threadIdx.x) >> 5);
    int nwarp = (int)((gridDim.x * blockDim.x) >> 5);
    int r = lane >> 2, c4 = lane & 3;
    for (int base = warp * 32; base < NTILES; base += nwarp * 32) {
        unsigned int tm = g_tilemax[base + lane];
        unsigned int mask = __ballot_sync(0xffffffffu, tm >= p);
        while (mask) {
            int b = __ffs(mask) - 1;
            mask &= mask - 1;
            int tt = base + b;
            int m0 = (tt >> 8) * 64, n0 = (tt & 255) * 32;
            for (int rr = 0; rr < 64; rr += 8) {
                const uint4* q = (const uint4*)(g_key16 + (size_t)(m0 + rr + r) * N_DIM + n0 + c4 * 8);
                uint4 v = *q;
                unsigned int w[4] = {v.x, v.y, v.z, v.w};
#pragma unroll
                for (int j = 0; j < 4; j++) {
                    unsigned int rlo = maxk16 - (w[j] & 0xffffu);
                    unsigned int rhi = maxk16 - (w[j] >> 16);
                    if (rlo < WINBINS) atomicAdd(&sh[rlo], 1u);
                    if (rhi < WINBINS) atomicAdd(&sh[rhi], 1u);
                }
            }
        }
    }
    __syncthreads();
    for (int i = threadIdx.x; i < WINBINS; i += blockDim.x)
        if (sh[i]) atomicAdd(&g_hist[i], sh[i]);
}

// ---------------- find cut: parallel prefix scan over 512 bins, +1 bin margin ----------------
__global__ void __launch_bounds__(512) cut_kernel() {
    __shared__ unsigned int pfx[WINBINS];
    int t = threadIdx.x;
    pfx[t] = g_hist[t];
    __syncthreads();
    for (int off = 1; off < WINBINS; off <<= 1) {
        unsigned int v = (t >= off) ? pfx[t - off] : 0u;
        __syncthreads();
        pfx[t] += v;
        __syncthreads();
    }
    unsigned int maxk16 = g_maxkey >> 16;
    if (pfx[t] >= TOPK && (t == 0 || pfx[t - 1] < TOPK))
        g_cutabs = maxk16 - (unsigned int)(t + 1);   // +1 bin margin
    if (t == WINBINS - 1 && pfx[t] < TOPK)
        g_cutabs = maxk16 - (unsigned int)WINBINS;
}

// ---------------- tile-pruned candidate collection (cutabs prune, exact) ----------------
__global__ void cand_kernel() {
    unsigned int cutabs = g_cutabs;
    int lane = threadIdx.x & 31;
    int warp = (int)((blockIdx.x * blockDim.x + threadIdx.x) >> 5);
    int nwarp = (int)((gridDim.x * blockDim.x) >> 5);
    int r = lane >> 2, c4 = lane & 3;
    for (int base = warp * 32; base < NTILES; base += nwarp * 32) {
        unsigned int tm = g_tilemax[base + lane];
        unsigned int mask = __ballot_sync(0xffffffffu, tm >= cutabs);
        while (mask) {
            int b = __ffs(mask) - 1;
            mask &= mask - 1;
            int tt = base + b;
            int m0 = (tt >> 8) * 64, n0 = (tt & 255) * 32;
            for (int rr = 0; rr < 64; rr += 8) {
                size_t rowoff = (size_t)(m0 + rr + r) * N_DIM + n0 + c4 * 8;
                const uint4* q = (const uint4*)(g_key16 + rowoff);
                uint4 v = *q;
                unsigned int w[4] = {v.x, v.y, v.z, v.w};
#pragma unroll
                for (int j = 0; j < 4; j++) {
                    if ((w[j] & 0xffffu) >= cutabs) {
                        unsigned int pos = atomicAdd(&g_cand_count, 1u);
                        if (pos < CAND_CAP) g_cand_idx[pos] = (unsigned int)(rowoff + 2 * j);
                    }
                    if ((w[j] >> 16) >= cutabs) {
                        unsigned int pos = atomicAdd(&g_cand_count, 1u);
                        if (pos < CAND_CAP) g_cand_idx[pos] = (unsigned int)(rowoff + 2 * j + 1);
                    }
                }
            }
        }
    }
}

// ---------------- refine: exact fp64 dot per candidate ----------------
__global__ void refine_kernel() {
    unsigned int count = g_cand_count;
    if (count > CAND_CAP) count = CAND_CAP;
    unsigned int warp = (blockIdx.x * blockDim.x + threadIdx.x) >> 5;
    unsigned int nwarp = (gridDim.x * blockDim.x) >> 5;
    int lane = threadIdx.x & 31;
    for (unsigned int c = warp; c < count; c += nwarp) {
        unsigned int idx = g_cand_idx[c];
        const float* a = g_md0f + (size_t)(idx >> 13) * HID;
        const float* b = g_md1f + (size_t)(idx & 8191u) * HID;
        double s = 0.0;
#pragma unroll
        for (int k = 0; k < HID / 32; k++)
            s += (double)a[k * 32 + lane] * (double)b[k * 32 + lane];
#pragma unroll
        for (int o = 16; o > 0; o >>= 1)
            s += __shfl_xor_sync(0xffffffffu, s, o);
        if (lane == 0) g_cand_ref[c] = s;
    }
}

// ---------------- rank-select on refined values (deterministic) ----------------
__global__ void __launch_bounds__(256) rank_kernel(float* __restrict__ idx_out) {
    unsigned int count = g_cand_count;
    if (count > CAND_CAP) count = CAND_CAP;
    unsigned int stride = gridDim.x * blockDim.x;
    for (unsigned int i = blockIdx.x * blockDim.x + threadIdx.x; i < count; i += stride) {
        double vi = g_cand_ref[i];
        unsigned int ii = g_cand_idx[i];
        unsigned int rank = 0;
        for (unsigned int j = 0; j < count; j++) {
            double vj = g_cand_ref[j];
            unsigned int ij = g_cand_idx[j];
            if (vj > vi || (vj == vi && ij < ii)) rank++;
        }
        if (rank < TOPK) {
            idx_out[rank * 2 + 0] = (float)(ii >> 13);
            idx_out[rank * 2 + 1] = (float)(ii & 8191u);
        }
    }
}

// ---------------- launch ----------------
extern "C" void kernel_launch(void* const* d_in, const int* in_sizes, int n_in,
                              void* d_out, int out_size) {
    const float* desc0 = (const float*)d_in[0];
    const float* desc1 = (const float*)d_in[1];
    const float* W0a = (const float*)d_in[2];
    const float* b0a = (const float*)d_in[3];
    const float* W0b = (const float*)d_in[4];
    const float* b0b = (const float*)d_in[5];
    const float* W1a = (const float*)d_in[6];
    const float* b1a = (const float*)d_in[7];
    const float* W1b = (const float*)d_in[8];
    const float* b1b = (const float*)d_in[9];

    float* out = (float*)d_out;
    long long simN = (long long)M_DIM * N_DIM;
    long long extra = (long long)out_size - simN;

    float* idx_out = nullptr;
    float* sim = out;
    if (extra >= 2 * TOPK) {  // tuple layout: [indices (TOPK*2)] [sim (M*N)]
        idx_out = out;
        sim = out + extra;
    }

    cudaFuncSetAttribute(gemm_mma_kernel,
                         cudaFuncAttributeMaxDynamicSharedMemorySize, GSMEM_BYTES);

    reset_kernel<<<1, 1024>>>();
    mlp_kernel<<<512, 256>>>(desc0, desc1, W0a, b0a, W0b, b0b, W1a, b1a, W1b, b1b);
    gemm_mma_kernel<<<dim3(N_DIM / 128, M_DIM / 128), 256, GSMEM_BYTES>>>(sim);

    if (idx_out) {
        tilesel_kernel<<<1, 512>>>();
        hist_kernel<<<128, 256>>>();
        cut_kernel<<<1, 512>>>();
        cand_kernel<<<128, 256>>>();
        refine_kernel<<<128, 256>>>();
        rank_kernel<<<64, 256>>>(idx_out);
    }
}

// round 13
// speedup vs baseline: 10.4463x; 1.0385x over previous
#include <cuda_runtime.h>
#include <cuda_fp16.h>
#include <cstdint>

#define M_DIM 8192
#define N_DIM 8192
#define IN_DIM 128
#define HID 256
#define TOPK 512
#define WINBINS 512
#define CAND_CAP (1 << 16)
#define NTILES (128 * 256)   // 64x32 warp tiles

// ---------------- device scratch (no allocations allowed) ----------------
__device__ __half g_md0h[M_DIM * HID];
__device__ __half g_md0l[M_DIM * HID];
__device__ __half g_md1h[N_DIM * HID];
__device__ __half g_md1l[N_DIM * HID];
__device__ float g_md0f[M_DIM * HID];
__device__ float g_md1f[N_DIM * HID];
__device__ unsigned short g_key16[(size_t)M_DIM * N_DIM];  // compact sort keys
__device__ unsigned short g_tilemax[NTILES];               // per 64x32 tile key max
__device__ unsigned int g_maxkey;
__device__ unsigned int g_cutabs;   // 16-bit key threshold (= p, provably <= true cut)
__device__ unsigned int g_cand_count;
__device__ unsigned int g_cand_idx[CAND_CAP];
__device__ double g_cand_ref[CAND_CAP];

__device__ __forceinline__ unsigned int fkey(float v) {
    unsigned int u = __float_as_uint(v);
    return (u & 0x80000000u) ? ~u : (u | 0x80000000u);
}

// ---------------- reset ----------------
__global__ void reset_kernel() {
    if (threadIdx.x == 0) { g_maxkey = 0; g_cand_count = 0; }
}

// ---------------- MLP (both descriptors in one grid) ----------------
__global__ void __launch_bounds__(256) mlp_kernel(
    const float* __restrict__ x0, const float* __restrict__ x1,
    const float* __restrict__ W0a, const float* __restrict__ b0a,
    const float* __restrict__ W0b, const float* __restrict__ b0b,
    const float* __restrict__ W1a, const float* __restrict__ b1a,
    const float* __restrict__ W1b, const float* __restrict__ b1b)
{
    __shared__ float xs[32 * IN_DIM];
    __shared__ float hs[32 * HID];
    int which = (blockIdx.x >= 256) ? 1 : 0;
    int blk = blockIdx.x & 255;
    const float* x = which ? x1 : x0;
    const float* Wa = which ? W1a : W0a;
    const float* ba = which ? b1a : b0a;
    const float* Wb = which ? W1b : W0b;
    const float* bb = which ? b1b : b0b;
    __half* outh = which ? g_md1h : g_md0h;
    __half* outl = which ? g_md1l : g_md0l;
    float* outf = which ? g_md1f : g_md0f;

    int tid = threadIdx.x;
    const float* xb = x + (size_t)blk * 32 * IN_DIM;

    {
        const float4* src = (const float4*)xb;
        float4* dst = (float4*)xs;
        for (int i = tid; i < 32 * IN_DIM / 4; i += 256) dst[i] = src[i];
    }
    __syncthreads();

    float acc[32];
    float bav = ba[tid];
#pragma unroll
    for (int r = 0; r < 32; r++) acc[r] = bav;

    const float4* xs4 = (const float4*)xs;
    for (int k = 0; k < IN_DIM; k += 4) {
        float w0 = Wa[(k + 0) * HID + tid];
        float w1 = Wa[(k + 1) * HID + tid];
        float w2 = Wa[(k + 2) * HID + tid];
        float w3 = Wa[(k + 3) * HID + tid];
#pragma unroll
        for (int r = 0; r < 32; r++) {
            float4 xv = xs4[r * (IN_DIM / 4) + (k >> 2)];
            acc[r] += xv.x * w0; acc[r] += xv.y * w1;
            acc[r] += xv.z * w2; acc[r] += xv.w * w3;
        }
    }
#pragma unroll
    for (int r = 0; r < 32; r++) hs[r * HID + tid] = fmaxf(acc[r], 0.0f);
    __syncthreads();

    float bbv = bb[tid];
#pragma unroll
    for (int r = 0; r < 32; r++) acc[r] = bbv;

    const float4* hs4 = (const float4*)hs;
    for (int k = 0; k < HID; k += 4) {
        float w0 = Wb[(k + 0) * HID + tid];
        float w1 = Wb[(k + 1) * HID + tid];
        float w2 = Wb[(k + 2) * HID + tid];
        float w3 = Wb[(k + 3) * HID + tid];
#pragma unroll
        for (int r = 0; r < 32; r++) {
            float4 hv = hs4[r * (HID / 4) + (k >> 2)];
            acc[r] += hv.x * w0; acc[r] += hv.y * w1;
            acc[r] += hv.z * w2; acc[r] += hv.w * w3;
        }
    }
#pragma unroll
    for (int r = 0; r < 32; r++) {
        float v = acc[r];
        __half hi = __float2half_rn(v);
        __half lo = __float2half_rn(v - __half2float(hi));
        size_t o = ((size_t)blk * 32 + r) * HID + tid;
        outh[o] = hi;
        outl[o] = lo;
        outf[o] = v;
    }
}

// ---------------- fp16 3-term NT GEMM, BK=32, 2 CTAs/SM, key16 + tilemax side outputs ----------------
#define BK 32
#define PITCH 40                       // halves per smem row (80B: 20-word rows -> 4-bank skew)
#define ROWB (PITCH * 2)               // 80 bytes
#define PLANE_BYTES (128 * ROWB)       // 10240
#define BUF_BYTES (4 * PLANE_BYTES)    // 40960 (Ah, Al, Bh, Bl)
#define GSMEM_BYTES (2 * BUF_BYTES)    // 81920 -> 2 CTAs/SM

__device__ __forceinline__ uint32_t smem_u32(const void* p) {
    uint32_t a;
    asm("{ .reg .u64 t; cvta.to.shared.u64 t, %1; cvt.u32.u64 %0, t; }" : "=r"(a) : "l"(p));
    return a;
}
__device__ __forceinline__ void cp16(uint32_t dst, const void* src) {
    asm volatile("cp.async.cg.shared.global [%0], [%1], 16;" :: "r"(dst), "l"(src) : "memory");
}
__device__ __forceinline__ void cp_commit() { asm volatile("cp.async.commit_group;" ::: "memory"); }
template <int N>
__device__ __forceinline__ void cp_wait() { asm volatile("cp.async.wait_group %0;" :: "n"(N) : "memory"); }

__device__ __forceinline__ void ldsm_x4(uint32_t& r0, uint32_t& r1, uint32_t& r2, uint32_t& r3,
                                        uint32_t addr) {
    asm volatile("ldmatrix.sync.aligned.m8n8.x4.shared.b16 {%0,%1,%2,%3}, [%4];"
                 : "=r"(r0), "=r"(r1), "=r"(r2), "=r"(r3) : "r"(addr));
}
__device__ __forceinline__ void ldsm_x2(uint32_t& r0, uint32_t& r1, uint32_t addr) {
    asm volatile("ldmatrix.sync.aligned.m8n8.x2.shared.b16 {%0,%1}, [%2];"
                 : "=r"(r0), "=r"(r1) : "r"(addr));
}

__device__ __forceinline__ void mma16816(float* d, uint32_t a0, uint32_t a1, uint32_t a2,
                                         uint32_t a3, uint32_t b0, uint32_t b1) {
    asm volatile(
        "mma.sync.aligned.m16n8k16.row.col.f32.f16.f16.f32 "
        "{%0,%1,%2,%3}, {%4,%5,%6,%7}, {%8,%9}, {%0,%1,%2,%3};"
        : "+f"(d[0]), "+f"(d[1]), "+f"(d[2]), "+f"(d[3])
        : "r"(a0), "r"(a1), "r"(a2), "r"(a3), "r"(b0), "r"(b1));
}

__global__ void __launch_bounds__(256, 2) gemm_mma_kernel(float* __restrict__ C) {
    extern __shared__ char smem[];
    uint32_t sb = smem_u32(smem);

    int tid = threadIdx.x;
    int wid = tid >> 5;
    int lane = tid & 31;
    int gid = lane >> 2;
    int tig = lane & 3;
    int m0 = blockIdx.y * 128;
    int n0 = blockIdx.x * 128;
    int wm = (wid >> 2) * 64;
    int wn = (wid & 3) * 32;

    float acc[4][4][4];
#pragma unroll
    for (int i = 0; i < 4; i++)
#pragma unroll
        for (int j = 0; j < 4; j++)
#pragma unroll
            for (int k = 0; k < 4; k++) acc[i][j][k] = 0.0f;

    const __half* planes_g[4] = {g_md0h, g_md0l, g_md1h, g_md1l};

    auto issue_chunk = [&](int kc, int buf) {
        uint32_t base = sb + buf * BUF_BYTES;
#pragma unroll
        for (int p = 0; p < 4; p++) {
            const __half* gp = planes_g[p];
            int row0 = (p < 2) ? m0 : n0;
#pragma unroll
            for (int j = 0; j < 2; j++) {
                int chunk = tid * 2 + j;       // 0..511
                int row = chunk >> 2;
                int seg = chunk & 3;           // 16B segment within 64B row
                uint32_t dst = base + p * PLANE_BYTES + row * ROWB + seg * 16;
                const void* src = gp + (size_t)(row0 + row) * HID + kc * BK + seg * 8;
                cp16(dst, src);
            }
        }
        cp_commit();
    };

    int a_rowadd = (lane & 7) + ((lane >> 3) & 1) * 8;
    int a_seg = (lane >> 4) * 16;
    int b_lane = lane & 15;
    int b_rowadd = b_lane & 7;
    int b_seg = ((b_lane >> 3) & 1) * 16;

    issue_chunk(0, 0);

    const int NCH = HID / BK;  // 8
    for (int kc = 0; kc < NCH; kc++) {
        int buf = kc & 1;
        if (kc + 1 < NCH) {
            issue_chunk(kc + 1, (kc + 1) & 1);
            cp_wait<1>();
        } else {
            cp_wait<0>();
        }
        __syncthreads();

        uint32_t bufb = sb + buf * BUF_BYTES;
        uint32_t pAh = bufb + 0 * PLANE_BYTES;
        uint32_t pAl = bufb + 1 * PLANE_BYTES;
        uint32_t pBh = bufb + 2 * PLANE_BYTES;
        uint32_t pBl = bufb + 3 * PLANE_BYTES;

#pragma unroll
        for (int ks = 0; ks < BK / 16; ks++) {
            uint32_t kso = ks * 32;
            uint32_t ah[4][4], al[4][4], bh[4][2], bl[4][2];
#pragma unroll
            for (int mt = 0; mt < 4; mt++) {
                uint32_t ro = (uint32_t)(wm + mt * 16 + a_rowadd) * ROWB + kso + a_seg;
                ldsm_x4(ah[mt][0], ah[mt][1], ah[mt][2], ah[mt][3], pAh + ro);
                ldsm_x4(al[mt][0], al[mt][1], al[mt][2], al[mt][3], pAl + ro);
            }
#pragma unroll
            for (int nt = 0; nt < 4; nt++) {
                uint32_t ro = (uint32_t)(wn + nt * 8 + b_rowadd) * ROWB + kso + b_seg;
                ldsm_x2(bh[nt][0], bh[nt][1], pBh + ro);
                ldsm_x2(bl[nt][0], bl[nt][1], pBl + ro);
            }
#pragma unroll
            for (int mt = 0; mt < 4; mt++)
#pragma unroll
                for (int nt = 0; nt < 4; nt++) {
                    mma16816(acc[mt][nt], ah[mt][0], ah[mt][1], ah[mt][2], ah[mt][3],
                             bh[nt][0], bh[nt][1]);
                    mma16816(acc[mt][nt], ah[mt][0], ah[mt][1], ah[mt][2], ah[mt][3],
                             bl[nt][0], bl[nt][1]);
                    mma16816(acc[mt][nt], al[mt][0], al[mt][1], al[mt][2], al[mt][3],
                             bh[nt][0], bh[nt][1]);
                }
        }
        __syncthreads();
    }

    // epilogue: store C + packed key16 plane + tile max + fused global max
    unsigned int mymax = 0;
#pragma unroll
    for (int mt = 0; mt < 4; mt++) {
        int r0 = m0 + wm + mt * 16 + gid;
#pragma unroll
        for (int nt = 0; nt < 4; nt++) {
            int col = n0 + wn + nt * 8 + 2 * tig;
            size_t o0 = (size_t)r0 * N_DIM + col;
            size_t o1 = (size_t)(r0 + 8) * N_DIM + col;
            *(float2*)(C + o0) = make_float2(acc[mt][nt][0], acc[mt][nt][1]);
            *(float2*)(C + o1) = make_float2(acc[mt][nt][2], acc[mt][nt][3]);
            unsigned int k0 = fkey(acc[mt][nt][0]), k1 = fkey(acc[mt][nt][1]);
            unsigned int k2 = fkey(acc[mt][nt][2]), k3 = fkey(acc[mt][nt][3]);
            *(uint32_t*)(g_key16 + o0) = (k0 >> 16) | (k1 & 0xffff0000u);
            *(uint32_t*)(g_key16 + o1) = (k2 >> 16) | (k3 & 0xffff0000u);
            mymax = max(max(mymax, max(k0, k1)), max(k2, k3));
        }
    }
#pragma unroll
    for (int s = 16; s > 0; s >>= 1)
        mymax = max(mymax, __shfl_xor_sync(0xffffffffu, mymax, s));

    // warp tile max -> g_tilemax (tile = 64 rows x 32 cols)
    if (lane == 0) {
        int mt = blockIdx.y * 2 + (wid >> 2);   // 0..127
        int nt = blockIdx.x * 4 + (wid & 3);    // 0..255
        g_tilemax[mt * 256 + nt] = (unsigned short)(mymax >> 16);
    }

    __shared__ unsigned int wmax[8];
    if (lane == 0) wmax[wid] = mymax;
    __syncthreads();
    if (tid == 0) {
        unsigned int m = wmax[0];
#pragma unroll
        for (int i = 1; i < 8; i++) m = max(m, wmax[i]);
        atomicMax(&g_maxkey, m);
    }
}

// ---------------- tilesel: cutabs = 512th-largest tile max (provably <= true cut, tight for spread data) ----------------
__global__ void __launch_bounds__(1024) tilesel_kernel() {
    __shared__ unsigned int h[WINBINS];
    __shared__ unsigned int pfx[WINBINS];
    int t = threadIdx.x;
    if (t < WINBINS) h[t] = 0;
    __syncthreads();
    unsigned int maxk16 = g_maxkey >> 16;
    for (int i = t; i < NTILES; i += 1024) {
        unsigned int rel = maxk16 - (unsigned int)g_tilemax[i];
        if (rel >= WINBINS) rel = WINBINS - 1;  // clamp deep tiles into last bin
        atomicAdd(&h[rel], 1u);
    }
    __syncthreads();
    if (t < WINBINS) pfx[t] = h[t];
    __syncthreads();
    for (int off = 1; off < WINBINS; off <<= 1) {
        unsigned int v = 0;
        if (t < WINBINS && t >= off) v = pfx[t - off];
        __syncthreads();
        if (t < WINBINS) pfx[t] += v;
        __syncthreads();
    }
    // smallest t with >= TOPK tile maxima at rel <= t  ->  cutabs = maxk16 - t
    if (t < WINBINS) {
        if (pfx[t] >= TOPK && (t == 0 || pfx[t - 1] < TOPK))
            g_cutabs = maxk16 - (unsigned int)t;
    }
}

// ---------------- tile-pruned candidate collection (cutabs prune, exact) ----------------
__global__ void cand_kernel() {
    unsigned int cutabs = g_cutabs;
    int lane = threadIdx.x & 31;
    int warp = (int)((blockIdx.x * blockDim.x + threadIdx.x) >> 5);
    int nwarp = (int)((gridDim.x * blockDim.x) >> 5);
    int r = lane >> 2, c4 = lane & 3;
    for (int base = warp * 32; base < NTILES; base += nwarp * 32) {
        unsigned int tm = g_tilemax[base + lane];
        unsigned int mask = __ballot_sync(0xffffffffu, tm >= cutabs);
        while (mask) {
            int b = __ffs(mask) - 1;
            mask &= mask - 1;
            int tt = base + b;
            int m0 = (tt >> 8) * 64, n0 = (tt & 255) * 32;
            for (int rr = 0; rr < 64; rr += 8) {
                size_t rowoff = (size_t)(m0 + rr + r) * N_DIM + n0 + c4 * 8;
                const uint4* q = (const uint4*)(g_key16 + rowoff);
                uint4 v = *q;
                unsigned int w[4] = {v.x, v.y, v.z, v.w};
#pragma unroll
                for (int j = 0; j < 4; j++) {
                    if ((w[j] & 0xffffu) >= cutabs) {
                        unsigned int pos = atomicAdd(&g_cand_count, 1u);
                        if (pos < CAND_CAP) g_cand_idx[pos] = (unsigned int)(rowoff + 2 * j);
                    }
                    if ((w[j] >> 16) >= cutabs) {
                        unsigned int pos = atomicAdd(&g_cand_count, 1u);
                        if (pos < CAND_CAP) g_cand_idx[pos] = (unsigned int)(rowoff + 2 * j + 1);
                    }
                }
            }
        }
    }
}

// ---------------- refine: exact fp64 dot per candidate ----------------
__global__ void refine_kernel() {
    unsigned int count = g_cand_count;
    if (count > CAND_CAP) count = CAND_CAP;
    unsigned int warp = (blockIdx.x * blockDim.x + threadIdx.x) >> 5;
    unsigned int nwarp = (gridDim.x * blockDim.x) >> 5;
    int lane = threadIdx.x & 31;
    for (unsigned int c = warp; c < count; c += nwarp) {
        unsigned int idx = g_cand_idx[c];
        const float* a = g_md0f + (size_t)(idx >> 13) * HID;
        const float* b = g_md1f + (size_t)(idx & 8191u) * HID;
        double s = 0.0;
#pragma unroll
        for (int k = 0; k < HID / 32; k++)
            s += (double)a[k * 32 + lane] * (double)b[k * 32 + lane];
#pragma unroll
        for (int o = 16; o > 0; o >>= 1)
            s += __shfl_xor_sync(0xffffffffu, s, o);
        if (lane == 0) g_cand_ref[c] = s;
    }
}

// ---------------- rank-select on refined values (deterministic) ----------------
__global__ void __launch_bounds__(256) rank_kernel(float* __restrict__ idx_out) {
    unsigned int count = g_cand_count;
    if (count > CAND_CAP) count = CAND_CAP;
    unsigned int stride = gridDim.x * blockDim.x;
    for (unsigned int i = blockIdx.x * blockDim.x + threadIdx.x; i < count; i += stride) {
        double vi = g_cand_ref[i];
        unsigned int ii = g_cand_idx[i];
        unsigned int rank = 0;
        for (unsigned int j = 0; j < count; j++) {
            double vj = g_cand_ref[j];
            unsigned int ij = g_cand_idx[j];
            if (vj > vi || (vj == vi && ij < ii)) rank++;
        }
        if (rank < TOPK) {
            idx_out[rank * 2 + 0] = (float)(ii >> 13);
            idx_out[rank * 2 + 1] = (float)(ii & 8191u);
        }
    }
}

// ---------------- launch ----------------
extern "C" void kernel_launch(void* const* d_in, const int* in_sizes, int n_in,
                              void* d_out, int out_size) {
    const float* desc0 = (const float*)d_in[0];
    const float* desc1 = (const float*)d_in[1];
    const float* W0a = (const float*)d_in[2];
    const float* b0a = (const float*)d_in[3];
    const float* W0b = (const float*)d_in[4];
    const float* b0b = (const float*)d_in[5];
    const float* W1a = (const float*)d_in[6];
    const float* b1a = (const float*)d_in[7];
    const float* W1b = (const float*)d_in[8];
    const float* b1b = (const float*)d_in[9];

    float* out = (float*)d_out;
    long long simN = (long long)M_DIM * N_DIM;
    long long extra = (long long)out_size - simN;

    float* idx_out = nullptr;
    float* sim = out;
    if (extra >= 2 * TOPK) {  // tuple layout: [indices (TOPK*2)] [sim (M*N)]
        idx_out = out;
        sim = out + extra;
    }

    cudaFuncSetAttribute(gemm_mma_kernel,
                         cudaFuncAttributeMaxDynamicSharedMemorySize, GSMEM_BYTES);

    reset_kernel<<<1, 32>>>();
    mlp_kernel<<<512, 256>>>(desc0, desc1, W0a, b0a, W0b, b0b, W1a, b1a, W1b, b1b);
    gemm_mma_kernel<<<dim3(N_DIM / 128, M_DIM / 128), 256, GSMEM_BYTES>>>(sim);

    if (idx_out) {
        tilesel_kernel<<<1, 1024>>>();
        cand_kernel<<<128, 256>>>();
        refine_kernel<<<128, 256>>>();
        rank_kernel<<<64, 256>>>(idx_out);
    }
}

// round 14
// speedup vs baseline: 10.8209x; 1.0359x over previous
#include <cuda_runtime.h>
#include <cuda_fp16.h>
#include <cstdint>

#define M_DIM 8192
#define N_DIM 8192
#define IN_DIM 128
#define HID 256
#define TOPK 512
#define WINBINS 512
#define CAND_CAP (1 << 16)
#define NTILES (128 * 256)   // 64x32 warp tiles

// ---------------- device scratch (no allocations allowed) ----------------
__device__ __half g_md0h[M_DIM * HID];
__device__ __half g_md0l[M_DIM * HID];
__device__ __half g_md1h[N_DIM * HID];
__device__ __half g_md1l[N_DIM * HID];
__device__ float g_md0f[M_DIM * HID];
__device__ float g_md1f[N_DIM * HID];
__device__ unsigned short g_tilemax[NTILES];   // per 64x32 tile key max
__device__ unsigned int g_maxkey;
__device__ unsigned int g_cutabs;              // 16-bit key threshold
__device__ unsigned int g_cand_count;
__device__ unsigned int g_cand_idx[CAND_CAP];
__device__ double g_cand_ref[CAND_CAP];

__device__ __forceinline__ unsigned int fkey(float v) {
    unsigned int u = __float_as_uint(v);
    return (u & 0x80000000u) ? ~u : (u | 0x80000000u);
}

// ---------------- MLP (both descriptors in one grid; block 0 resets scalars) ----------------
__global__ void __launch_bounds__(256) mlp_kernel(
    const float* __restrict__ x0, const float* __restrict__ x1,
    const float* __restrict__ W0a, const float* __restrict__ b0a,
    const float* __restrict__ W0b, const float* __restrict__ b0b,
    const float* __restrict__ W1a, const float* __restrict__ b1a,
    const float* __restrict__ W1b, const float* __restrict__ b1b)
{
    __shared__ float xs[32 * IN_DIM];
    __shared__ float hs[32 * HID];
    if (blockIdx.x == 0 && threadIdx.x == 0) { g_maxkey = 0; g_cand_count = 0; }

    int which = (blockIdx.x >= 256) ? 1 : 0;
    int blk = blockIdx.x & 255;
    const float* x = which ? x1 : x0;
    const float* Wa = which ? W1a : W0a;
    const float* ba = which ? b1a : b0a;
    const float* Wb = which ? W1b : W0b;
    const float* bb = which ? b1b : b0b;
    __half* outh = which ? g_md1h : g_md0h;
    __half* outl = which ? g_md1l : g_md0l;
    float* outf = which ? g_md1f : g_md0f;

    int tid = threadIdx.x;
    const float* xb = x + (size_t)blk * 32 * IN_DIM;

    {
        const float4* src = (const float4*)xb;
        float4* dst = (float4*)xs;
        for (int i = tid; i < 32 * IN_DIM / 4; i += 256) dst[i] = src[i];
    }
    __syncthreads();

    float acc[32];
    float bav = ba[tid];
#pragma unroll
    for (int r = 0; r < 32; r++) acc[r] = bav;

    const float4* xs4 = (const float4*)xs;
    for (int k = 0; k < IN_DIM; k += 4) {
        float w0 = Wa[(k + 0) * HID + tid];
        float w1 = Wa[(k + 1) * HID + tid];
        float w2 = Wa[(k + 2) * HID + tid];
        float w3 = Wa[(k + 3) * HID + tid];
#pragma unroll
        for (int r = 0; r < 32; r++) {
            float4 xv = xs4[r * (IN_DIM / 4) + (k >> 2)];
            acc[r] += xv.x * w0; acc[r] += xv.y * w1;
            acc[r] += xv.z * w2; acc[r] += xv.w * w3;
        }
    }
#pragma unroll
    for (int r = 0; r < 32; r++) hs[r * HID + tid] = fmaxf(acc[r], 0.0f);
    __syncthreads();

    float bbv = bb[tid];
#pragma unroll
    for (int r = 0; r < 32; r++) acc[r] = bbv;

    const float4* hs4 = (const float4*)hs;
    for (int k = 0; k < HID; k += 4) {
        float w0 = Wb[(k + 0) * HID + tid];
        float w1 = Wb[(k + 1) * HID + tid];
        float w2 = Wb[(k + 2) * HID + tid];
        float w3 = Wb[(k + 3) * HID + tid];
#pragma unroll
        for (int r = 0; r < 32; r++) {
            float4 hv = hs4[r * (HID / 4) + (k >> 2)];
            acc[r] += hv.x * w0; acc[r] += hv.y * w1;
            acc[r] += hv.z * w2; acc[r] += hv.w * w3;
        }
    }
#pragma unroll
    for (int r = 0; r < 32; r++) {
        float v = acc[r];
        __half hi = __float2half_rn(v);
        __half lo = __float2half_rn(v - __half2float(hi));
        size_t o = ((size_t)blk * 32 + r) * HID + tid;
        outh[o] = hi;
        outl[o] = lo;
        outf[o] = v;
    }
}

// ---------------- fp16 3-term NT GEMM, BK=32, 2 CTAs/SM, tilemax side output ----------------
#define BK 32
#define PITCH 40                       // halves per smem row (80B: 20-word rows -> 4-bank skew)
#define ROWB (PITCH * 2)               // 80 bytes
#define PLANE_BYTES (128 * ROWB)       // 10240
#define BUF_BYTES (4 * PLANE_BYTES)    // 40960 (Ah, Al, Bh, Bl)
#define GSMEM_BYTES (2 * BUF_BYTES)    // 81920 -> 2 CTAs/SM

__device__ __forceinline__ uint32_t smem_u32(const void* p) {
    uint32_t a;
    asm("{ .reg .u64 t; cvta.to.shared.u64 t, %1; cvt.u32.u64 %0, t; }" : "=r"(a) : "l"(p));
    return a;
}
__device__ __forceinline__ void cp16(uint32_t dst, const void* src) {
    asm volatile("cp.async.cg.shared.global [%0], [%1], 16;" :: "r"(dst), "l"(src) : "memory");
}
__device__ __forceinline__ void cp_commit() { asm volatile("cp.async.commit_group;" ::: "memory"); }
template <int N>
__device__ __forceinline__ void cp_wait() { asm volatile("cp.async.wait_group %0;" :: "n"(N) : "memory"); }

__device__ __forceinline__ void ldsm_x4(uint32_t& r0, uint32_t& r1, uint32_t& r2, uint32_t& r3,
                                        uint32_t addr) {
    asm volatile("ldmatrix.sync.aligned.m8n8.x4.shared.b16 {%0,%1,%2,%3}, [%4];"
                 : "=r"(r0), "=r"(r1), "=r"(r2), "=r"(r3) : "r"(addr));
}
__device__ __forceinline__ void ldsm_x2(uint32_t& r0, uint32_t& r1, uint32_t addr) {
    asm volatile("ldmatrix.sync.aligned.m8n8.x2.shared.b16 {%0,%1}, [%2];"
                 : "=r"(r0), "=r"(r1) : "r"(addr));
}

__device__ __forceinline__ void mma16816(float* d, uint32_t a0, uint32_t a1, uint32_t a2,
                                         uint32_t a3, uint32_t b0, uint32_t b1) {
    asm volatile(
        "mma.sync.aligned.m16n8k16.row.col.f32.f16.f16.f32 "
        "{%0,%1,%2,%3}, {%4,%5,%6,%7}, {%8,%9}, {%0,%1,%2,%3};"
        : "+f"(d[0]), "+f"(d[1]), "+f"(d[2]), "+f"(d[3])
        : "r"(a0), "r"(a1), "r"(a2), "r"(a3), "r"(b0), "r"(b1));
}

__global__ void __launch_bounds__(256, 2) gemm_mma_kernel(float* __restrict__ C) {
    extern __shared__ char smem[];
    uint32_t sb = smem_u32(smem);

    int tid = threadIdx.x;
    int wid = tid >> 5;
    int lane = tid & 31;
    int gid = lane >> 2;
    int tig = lane & 3;
    int m0 = blockIdx.y * 128;
    int n0 = blockIdx.x * 128;
    int wm = (wid >> 2) * 64;
    int wn = (wid & 3) * 32;

    float acc[4][4][4];
#pragma unroll
    for (int i = 0; i < 4; i++)
#pragma unroll
        for (int j = 0; j < 4; j++)
#pragma unroll
            for (int k = 0; k < 4; k++) acc[i][j][k] = 0.0f;

    const __half* planes_g[4] = {g_md0h, g_md0l, g_md1h, g_md1l};

    auto issue_chunk = [&](int kc, int buf) {
        uint32_t base = sb + buf * BUF_BYTES;
#pragma unroll
        for (int p = 0; p < 4; p++) {
            const __half* gp = planes_g[p];
            int row0 = (p < 2) ? m0 : n0;
#pragma unroll
            for (int j = 0; j < 2; j++) {
                int chunk = tid * 2 + j;       // 0..511
                int row = chunk >> 2;
                int seg = chunk & 3;           // 16B segment within 64B row
                uint32_t dst = base + p * PLANE_BYTES + row * ROWB + seg * 16;
                const void* src = gp + (size_t)(row0 + row) * HID + kc * BK + seg * 8;
                cp16(dst, src);
            }
        }
        cp_commit();
    };

    int a_rowadd = (lane & 7) + ((lane >> 3) & 1) * 8;
    int a_seg = (lane >> 4) * 16;
    int b_lane = lane & 15;
    int b_rowadd = b_lane & 7;
    int b_seg = ((b_lane >> 3) & 1) * 16;

    issue_chunk(0, 0);

    const int NCH = HID / BK;  // 8
    for (int kc = 0; kc < NCH; kc++) {
        int buf = kc & 1;
        if (kc + 1 < NCH) {
            issue_chunk(kc + 1, (kc + 1) & 1);
            cp_wait<1>();
        } else {
            cp_wait<0>();
        }
        __syncthreads();

        uint32_t bufb = sb + buf * BUF_BYTES;
        uint32_t pAh = bufb + 0 * PLANE_BYTES;
        uint32_t pAl = bufb + 1 * PLANE_BYTES;
        uint32_t pBh = bufb + 2 * PLANE_BYTES;
        uint32_t pBl = bufb + 3 * PLANE_BYTES;

#pragma unroll
        for (int ks = 0; ks < BK / 16; ks++) {
            uint32_t kso = ks * 32;
            uint32_t ah[4][4], al[4][4], bh[4][2], bl[4][2];
#pragma unroll
            for (int mt = 0; mt < 4; mt++) {
                uint32_t ro = (uint32_t)(wm + mt * 16 + a_rowadd) * ROWB + kso + a_seg;
                ldsm_x4(ah[mt][0], ah[mt][1], ah[mt][2], ah[mt][3], pAh + ro);
                ldsm_x4(al[mt][0], al[mt][1], al[mt][2], al[mt][3], pAl + ro);
            }
#pragma unroll
            for (int nt = 0; nt < 4; nt++) {
                uint32_t ro = (uint32_t)(wn + nt * 8 + b_rowadd) * ROWB + kso + b_seg;
                ldsm_x2(bh[nt][0], bh[nt][1], pBh + ro);
                ldsm_x2(bl[nt][0], bl[nt][1], pBl + ro);
            }
#pragma unroll
            for (int mt = 0; mt < 4; mt++)
#pragma unroll
                for (int nt = 0; nt < 4; nt++) {
                    mma16816(acc[mt][nt], ah[mt][0], ah[mt][1], ah[mt][2], ah[mt][3],
                             bh[nt][0], bh[nt][1]);
                    mma16816(acc[mt][nt], ah[mt][0], ah[mt][1], ah[mt][2], ah[mt][3],
                             bl[nt][0], bl[nt][1]);
                    mma16816(acc[mt][nt], al[mt][0], al[mt][1], al[mt][2], al[mt][3],
                             bh[nt][0], bh[nt][1]);
                }
        }
        __syncthreads();
    }

    // epilogue: store C + tile max + fused global max (no key plane)
    unsigned int mymax = 0;
#pragma unroll
    for (int mt = 0; mt < 4; mt++) {
        int r0 = m0 + wm + mt * 16 + gid;
#pragma unroll
        for (int nt = 0; nt < 4; nt++) {
            int col = n0 + wn + nt * 8 + 2 * tig;
            size_t o0 = (size_t)r0 * N_DIM + col;
            size_t o1 = (size_t)(r0 + 8) * N_DIM + col;
            *(float2*)(C + o0) = make_float2(acc[mt][nt][0], acc[mt][nt][1]);
            *(float2*)(C + o1) = make_float2(acc[mt][nt][2], acc[mt][nt][3]);
            unsigned int k0 = fkey(acc[mt][nt][0]), k1 = fkey(acc[mt][nt][1]);
            unsigned int k2 = fkey(acc[mt][nt][2]), k3 = fkey(acc[mt][nt][3]);
            mymax = max(max(mymax, max(k0, k1)), max(k2, k3));
        }
    }
#pragma unroll
    for (int s = 16; s > 0; s >>= 1)
        mymax = max(mymax, __shfl_xor_sync(0xffffffffu, mymax, s));

    if (lane == 0) {
        int mt = blockIdx.y * 2 + (wid >> 2);
        int nt = blockIdx.x * 4 + (wid & 3);
        g_tilemax[mt * 256 + nt] = (unsigned short)(mymax >> 16);
    }

    __shared__ unsigned int wmax[8];
    if (lane == 0) wmax[wid] = mymax;
    __syncthreads();
    if (tid == 0) {
        unsigned int m = wmax[0];
#pragma unroll
        for (int i = 1; i < 8; i++) m = max(m, wmax[i]);
        atomicMax(&g_maxkey, m);
    }
}

// ---------------- tilesel: cutabs = 512th-largest tile max (deep tiles skipped, no hot bin) ----------------
__global__ void __launch_bounds__(1024) tilesel_kernel() {
    __shared__ unsigned int h[WINBINS];
    __shared__ unsigned int pfx[WINBINS];
    int t = threadIdx.x;
    if (t < WINBINS) h[t] = 0;
    __syncthreads();
    unsigned int maxk16 = g_maxkey >> 16;
    for (int i = t; i < NTILES; i += 1024) {
        unsigned int rel = maxk16 - (unsigned int)g_tilemax[i];
        if (rel < WINBINS) atomicAdd(&h[rel], 1u);  // deep tiles skipped (no hot-bin convoy)
    }
    __syncthreads();
    if (t < WINBINS) pfx[t] = h[t];
    __syncthreads();
    for (int off = 1; off < WINBINS; off <<= 1) {
        unsigned int v = 0;
        if (t < WINBINS && t >= off) v = pfx[t - off];
        __syncthreads();
        if (t < WINBINS) pfx[t] += v;
        __syncthreads();
    }
    if (t < WINBINS) {
        if (pfx[t] >= TOPK && (t == 0 || pfx[t - 1] < TOPK))
            g_cutabs = maxk16 - (unsigned int)t;
        if (t == WINBINS - 1 && pfx[t] < TOPK)
            g_cutabs = maxk16 - (unsigned int)(WINBINS - 1);  // fallback: scan all window tiles
    }
}

// ---------------- tile-pruned candidate collection: keys computed from fp32 sim ----------------
__global__ void cand_kernel(const float* __restrict__ C) {
    unsigned int cutabs = g_cutabs;
    int lane = threadIdx.x & 31;
    int warp = (int)((blockIdx.x * blockDim.x + threadIdx.x) >> 5);
    int nwarp = (int)((gridDim.x * blockDim.x) >> 5);
    int r4 = lane >> 3;           // row within 4-row pass
    int c8 = (lane & 7) * 4;      // float4 column start
    for (int base = warp * 32; base < NTILES; base += nwarp * 32) {
        unsigned int tm = g_tilemax[base + lane];
        unsigned int mask = __ballot_sync(0xffffffffu, tm >= cutabs);
        while (mask) {
            int b = __ffs(mask) - 1;
            mask &= mask - 1;
            int tt = base + b;
            int m0 = (tt >> 8) * 64, n0 = (tt & 255) * 32;
#pragma unroll 4
            for (int it = 0; it < 16; it++) {
                size_t off = (size_t)(m0 + it * 4 + r4) * N_DIM + n0 + c8;
                float4 v = *(const float4*)(C + off);
                float vv[4] = {v.x, v.y, v.z, v.w};
#pragma unroll
                for (int j = 0; j < 4; j++) {
                    if ((fkey(vv[j]) >> 16) >= cutabs) {
                        unsigned int pos = atomicAdd(&g_cand_count, 1u);
                        if (pos < CAND_CAP) g_cand_idx[pos] = (unsigned int)(off + j);
                    }
                }
            }
        }
    }
}

// ---------------- refine: exact fp64 dot per candidate ----------------
__global__ void refine_kernel() {
    unsigned int count = g_cand_count;
    if (count > CAND_CAP) count = CAND_CAP;
    unsigned int warp = (blockIdx.x * blockDim.x + threadIdx.x) >> 5;
    unsigned int nwarp = (gridDim.x * blockDim.x) >> 5;
    int lane = threadIdx.x & 31;
    for (unsigned int c = warp; c < count; c += nwarp) {
        unsigned int idx = g_cand_idx[c];
        const float* a = g_md0f + (size_t)(idx >> 13) * HID;
        const float* b = g_md1f + (size_t)(idx & 8191u) * HID;
        double s = 0.0;
#pragma unroll
        for (int k = 0; k < HID / 32; k++)
            s += (double)a[k * 32 + lane] * (double)b[k * 32 + lane];
#pragma unroll
        for (int o = 16; o > 0; o >>= 1)
            s += __shfl_xor_sync(0xffffffffu, s, o);
        if (lane == 0) g_cand_ref[c] = s;
    }
}

// ---------------- rank-select on refined values (deterministic) ----------------
__global__ void __launch_bounds__(256) rank_kernel(float* __restrict__ idx_out) {
    unsigned int count = g_cand_count;
    if (count > CAND_CAP) count = CAND_CAP;
    unsigned int stride = gridDim.x * blockDim.x;
    for (unsigned int i = blockIdx.x * blockDim.x + threadIdx.x; i < count; i += stride) {
        double vi = g_cand_ref[i];
        unsigned int ii = g_cand_idx[i];
        unsigned int rank = 0;
        for (unsigned int j = 0; j < count; j++) {
            double vj = g_cand_ref[j];
            unsigned int ij = g_cand_idx[j];
            if (vj > vi || (vj == vi && ij < ii)) rank++;
        }
        if (rank < TOPK) {
            idx_out[rank * 2 + 0] = (float)(ii >> 13);
            idx_out[rank * 2 + 1] = (float)(ii & 8191u);
        }
    }
}

// ---------------- launch ----------------
extern "C" void kernel_launch(void* const* d_in, const int* in_sizes, int n_in,
                              void* d_out, int out_size) {
    const float* desc0 = (const float*)d_in[0];
    const float* desc1 = (const float*)d_in[1];
    const float* W0a = (const float*)d_in[2];
    const float* b0a = (const float*)d_in[3];
    const float* W0b = (const float*)d_in[4];
    const float* b0b = (const float*)d_in[5];
    const float* W1a = (const float*)d_in[6];
    const float* b1a = (const float*)d_in[7];
    const float* W1b = (const float*)d_in[8];
    const float* b1b = (const float*)d_in[9];

    float* out = (float*)d_out;
    long long simN = (long long)M_DIM * N_DIM;
    long long extra = (long long)out_size - simN;

    float* idx_out = nullptr;
    float* sim = out;
    if (extra >= 2 * TOPK) {  // tuple layout: [indices (TOPK*2)] [sim (M*N)]
        idx_out = out;
        sim = out + extra;
    }

    cudaFuncSetAttribute(gemm_mma_kernel,
                         cudaFuncAttributeMaxDynamicSharedMemorySize, GSMEM_BYTES);

    mlp_kernel<<<512, 256>>>(desc0, desc1, W0a, b0a, W0b, b0b, W1a, b1a, W1b, b1b);
    gemm_mma_kernel<<<dim3(N_DIM / 128, M_DIM / 128), 256, GSMEM_BYTES>>>(sim);

    if (idx_out) {
        tilesel_kernel<<<1, 1024>>>();
        cand_kernel<<<128, 256>>>(sim);
        refine_kernel<<<128, 256>>>();
        rank_kernel<<<64, 256>>>(idx_out);
    }
}

// round 15
// speedup vs baseline: 11.3975x; 1.0533x over previous
#include <cuda_runtime.h>
#include <cuda_fp16.h>
#include <cstdint>

#define M_DIM 8192
#define N_DIM 8192
#define IN_DIM 128
#define HID 256
#define TOPK 512
#define WINBINS 512
#define CAND_CAP (1 << 16)
#define NTILES (128 * 256)   // 64x32 warp tiles

// ---------------- device scratch (no allocations allowed) ----------------
__device__ __half g_md0h[M_DIM * HID];
__device__ __half g_md0l[M_DIM * HID];
__device__ __half g_md1h[N_DIM * HID];
__device__ __half g_md1l[N_DIM * HID];
__device__ float g_md0f[M_DIM * HID];
__device__ float g_md1f[N_DIM * HID];
__device__ unsigned short g_tilemax[NTILES];   // per 64x32 tile key max
__device__ unsigned int g_maxkey;
__device__ unsigned int g_cutabs;              // 16-bit key threshold
__device__ unsigned int g_tileq[NTILES];       // qualifying tile ids
__device__ unsigned int g_tileq_count;
__device__ unsigned int g_cand_count;
__device__ unsigned int g_cand_idx[CAND_CAP];
__device__ double g_cand_ref[CAND_CAP];

__device__ __forceinline__ unsigned int fkey(float v) {
    unsigned int u = __float_as_uint(v);
    return (u & 0x80000000u) ? ~u : (u | 0x80000000u);
}

// ---------------- MLP (both descriptors in one grid; block 0 resets scalars) ----------------
__global__ void __launch_bounds__(256) mlp_kernel(
    const float* __restrict__ x0, const float* __restrict__ x1,
    const float* __restrict__ W0a, const float* __restrict__ b0a,
    const float* __restrict__ W0b, const float* __restrict__ b0b,
    const float* __restrict__ W1a, const float* __restrict__ b1a,
    const float* __restrict__ W1b, const float* __restrict__ b1b)
{
    __shared__ float xs[32 * IN_DIM];
    __shared__ float hs[32 * HID];
    if (blockIdx.x == 0 && threadIdx.x == 0) {
        g_maxkey = 0; g_cand_count = 0; g_tileq_count = 0;
    }

    int which = (blockIdx.x >= 256) ? 1 : 0;
    int blk = blockIdx.x & 255;
    const float* x = which ? x1 : x0;
    const float* Wa = which ? W1a : W0a;
    const float* ba = which ? b1a : b0a;
    const float* Wb = which ? W1b : W0b;
    const float* bb = which ? b1b : b0b;
    __half* outh = which ? g_md1h : g_md0h;
    __half* outl = which ? g_md1l : g_md0l;
    float* outf = which ? g_md1f : g_md0f;

    int tid = threadIdx.x;
    const float* xb = x + (size_t)blk * 32 * IN_DIM;

    {
        const float4* src = (const float4*)xb;
        float4* dst = (float4*)xs;
        for (int i = tid; i < 32 * IN_DIM / 4; i += 256) dst[i] = src[i];
    }
    __syncthreads();

    float acc[32];
    float bav = ba[tid];
#pragma unroll
    for (int r = 0; r < 32; r++) acc[r] = bav;

    const float4* xs4 = (const float4*)xs;
    for (int k = 0; k < IN_DIM; k += 4) {
        float w0 = Wa[(k + 0) * HID + tid];
        float w1 = Wa[(k + 1) * HID + tid];
        float w2 = Wa[(k + 2) * HID + tid];
        float w3 = Wa[(k + 3) * HID + tid];
#pragma unroll
        for (int r = 0; r < 32; r++) {
            float4 xv = xs4[r * (IN_DIM / 4) + (k >> 2)];
            acc[r] += xv.x * w0; acc[r] += xv.y * w1;
            acc[r] += xv.z * w2; acc[r] += xv.w * w3;
        }
    }
#pragma unroll
    for (int r = 0; r < 32; r++) hs[r * HID + tid] = fmaxf(acc[r], 0.0f);
    __syncthreads();

    float bbv = bb[tid];
#pragma unroll
    for (int r = 0; r < 32; r++) acc[r] = bbv;

    const float4* hs4 = (const float4*)hs;
    for (int k = 0; k < HID; k += 4) {
        float w0 = Wb[(k + 0) * HID + tid];
        float w1 = Wb[(k + 1) * HID + tid];
        float w2 = Wb[(k + 2) * HID + tid];
        float w3 = Wb[(k + 3) * HID + tid];
#pragma unroll
        for (int r = 0; r < 32; r++) {
            float4 hv = hs4[r * (HID / 4) + (k >> 2)];
            acc[r] += hv.x * w0; acc[r] += hv.y * w1;
            acc[r] += hv.z * w2; acc[r] += hv.w * w3;
        }
    }
#pragma unroll
    for (int r = 0; r < 32; r++) {
        float v = acc[r];
        __half hi = __float2half_rn(v);
        __half lo = __float2half_rn(v - __half2float(hi));
        size_t o = ((size_t)blk * 32 + r) * HID + tid;
        outh[o] = hi;
        outl[o] = lo;
        outf[o] = v;
    }
}

// ---------------- fp16 3-term NT GEMM, BK=32, 2 CTAs/SM, tilemax side output ----------------
#define BK 32
#define PITCH 40                       // halves per smem row (80B: 20-word rows -> 4-bank skew)
#define ROWB (PITCH * 2)               // 80 bytes
#define PLANE_BYTES (128 * ROWB)       // 10240
#define BUF_BYTES (4 * PLANE_BYTES)    // 40960 (Ah, Al, Bh, Bl)
#define GSMEM_BYTES (2 * BUF_BYTES)    // 81920 -> 2 CTAs/SM

__device__ __forceinline__ uint32_t smem_u32(const void* p) {
    uint32_t a;
    asm("{ .reg .u64 t; cvta.to.shared.u64 t, %1; cvt.u32.u64 %0, t; }" : "=r"(a) : "l"(p));
    return a;
}
__device__ __forceinline__ void cp16(uint32_t dst, const void* src) {
    asm volatile("cp.async.cg.shared.global [%0], [%1], 16;" :: "r"(dst), "l"(src) : "memory");
}
__device__ __forceinline__ void cp_commit() { asm volatile("cp.async.commit_group;" ::: "memory"); }
template <int N>
__device__ __forceinline__ void cp_wait() { asm volatile("cp.async.wait_group %0;" :: "n"(N) : "memory"); }

__device__ __forceinline__ void ldsm_x4(uint32_t& r0, uint32_t& r1, uint32_t& r2, uint32_t& r3,
                                        uint32_t addr) {
    asm volatile("ldmatrix.sync.aligned.m8n8.x4.shared.b16 {%0,%1,%2,%3}, [%4];"
                 : "=r"(r0), "=r"(r1), "=r"(r2), "=r"(r3) : "r"(addr));
}
__device__ __forceinline__ void ldsm_x2(uint32_t& r0, uint32_t& r1, uint32_t addr) {
    asm volatile("ldmatrix.sync.aligned.m8n8.x2.shared.b16 {%0,%1}, [%2];"
                 : "=r"(r0), "=r"(r1) : "r"(addr));
}

__device__ __forceinline__ void mma16816(float* d, uint32_t a0, uint32_t a1, uint32_t a2,
                                         uint32_t a3, uint32_t b0, uint32_t b1) {
    asm volatile(
        "mma.sync.aligned.m16n8k16.row.col.f32.f16.f16.f32 "
        "{%0,%1,%2,%3}, {%4,%5,%6,%7}, {%8,%9}, {%0,%1,%2,%3};"
        : "+f"(d[0]), "+f"(d[1]), "+f"(d[2]), "+f"(d[3])
        : "r"(a0), "r"(a1), "r"(a2), "r"(a3), "r"(b0), "r"(b1));
}

__global__ void __launch_bounds__(256, 2) gemm_mma_kernel(float* __restrict__ C) {
    extern __shared__ char smem[];
    uint32_t sb = smem_u32(smem);

    int tid = threadIdx.x;
    int wid = tid >> 5;
    int lane = tid & 31;
    int gid = lane >> 2;
    int tig = lane & 3;
    int m0 = blockIdx.y * 128;
    int n0 = blockIdx.x * 128;
    int wm = (wid >> 2) * 64;
    int wn = (wid & 3) * 32;

    float acc[4][4][4];
#pragma unroll
    for (int i = 0; i < 4; i++)
#pragma unroll
        for (int j = 0; j < 4; j++)
#pragma unroll
            for (int k = 0; k < 4; k++) acc[i][j][k] = 0.0f;

    const __half* planes_g[4] = {g_md0h, g_md0l, g_md1h, g_md1l};

    auto issue_chunk = [&](int kc, int buf) {
        uint32_t base = sb + buf * BUF_BYTES;
#pragma unroll
        for (int p = 0; p < 4; p++) {
            const __half* gp = planes_g[p];
            int row0 = (p < 2) ? m0 : n0;
#pragma unroll
            for (int j = 0; j < 2; j++) {
                int chunk = tid * 2 + j;       // 0..511
                int row = chunk >> 2;
                int seg = chunk & 3;           // 16B segment within 64B row
                uint32_t dst = base + p * PLANE_BYTES + row * ROWB + seg * 16;
                const void* src = gp + (size_t)(row0 + row) * HID + kc * BK + seg * 8;
                cp16(dst, src);
            }
        }
        cp_commit();
    };

    int a_rowadd = (lane & 7) + ((lane >> 3) & 1) * 8;
    int a_seg = (lane >> 4) * 16;
    int b_lane = lane & 15;
    int b_rowadd = b_lane & 7;
    int b_seg = ((b_lane >> 3) & 1) * 16;

    issue_chunk(0, 0);

    const int NCH = HID / BK;  // 8
    for (int kc = 0; kc < NCH; kc++) {
        int buf = kc & 1;
        if (kc + 1 < NCH) {
            issue_chunk(kc + 1, (kc + 1) & 1);
            cp_wait<1>();
        } else {
            cp_wait<0>();
        }
        __syncthreads();

        uint32_t bufb = sb + buf * BUF_BYTES;
        uint32_t pAh = bufb + 0 * PLANE_BYTES;
        uint32_t pAl = bufb + 1 * PLANE_BYTES;
        uint32_t pBh = bufb + 2 * PLANE_BYTES;
        uint32_t pBl = bufb + 3 * PLANE_BYTES;

#pragma unroll
        for (int ks = 0; ks < BK / 16; ks++) {
            uint32_t kso = ks * 32;
            uint32_t ah[4][4], al[4][4], bh[4][2], bl[4][2];
#pragma unroll
            for (int mt = 0; mt < 4; mt++) {
                uint32_t ro = (uint32_t)(wm + mt * 16 + a_rowadd) * ROWB + kso + a_seg;
                ldsm_x4(ah[mt][0], ah[mt][1], ah[mt][2], ah[mt][3], pAh + ro);
                ldsm_x4(al[mt][0], al[mt][1], al[mt][2], al[mt][3], pAl + ro);
            }
#pragma unroll
            for (int nt = 0; nt < 4; nt++) {
                uint32_t ro = (uint32_t)(wn + nt * 8 + b_rowadd) * ROWB + kso + b_seg;
                ldsm_x2(bh[nt][0], bh[nt][1], pBh + ro);
                ldsm_x2(bl[nt][0], bl[nt][1], pBl + ro);
            }
#pragma unroll
            for (int mt = 0; mt < 4; mt++)
#pragma unroll
                for (int nt = 0; nt < 4; nt++) {
                    mma16816(acc[mt][nt], ah[mt][0], ah[mt][1], ah[mt][2], ah[mt][3],
                             bh[nt][0], bh[nt][1]);
                    mma16816(acc[mt][nt], ah[mt][0], ah[mt][1], ah[mt][2], ah[mt][3],
                             bl[nt][0], bl[nt][1]);
                    mma16816(acc[mt][nt], al[mt][0], al[mt][1], al[mt][2], al[mt][3],
                             bh[nt][0], bh[nt][1]);
                }
        }
        __syncthreads();
    }

    // epilogue: store C + tile max + fused global max
    unsigned int mymax = 0;
#pragma unroll
    for (int mt = 0; mt < 4; mt++) {
        int r0 = m0 + wm + mt * 16 + gid;
#pragma unroll
        for (int nt = 0; nt < 4; nt++) {
            int col = n0 + wn + nt * 8 + 2 * tig;
            size_t o0 = (size_t)r0 * N_DIM + col;
            size_t o1 = (size_t)(r0 + 8) * N_DIM + col;
            *(float2*)(C + o0) = make_float2(acc[mt][nt][0], acc[mt][nt][1]);
            *(float2*)(C + o1) = make_float2(acc[mt][nt][2], acc[mt][nt][3]);
            unsigned int k0 = fkey(acc[mt][nt][0]), k1 = fkey(acc[mt][nt][1]);
            unsigned int k2 = fkey(acc[mt][nt][2]), k3 = fkey(acc[mt][nt][3]);
            mymax = max(max(mymax, max(k0, k1)), max(k2, k3));
        }
    }
#pragma unroll
    for (int s = 16; s > 0; s >>= 1)
        mymax = max(mymax, __shfl_xor_sync(0xffffffffu, mymax, s));

    if (lane == 0) {
        int mt = blockIdx.y * 2 + (wid >> 2);
        int nt = blockIdx.x * 4 + (wid & 3);
        g_tilemax[mt * 256 + nt] = (unsigned short)(mymax >> 16);
    }

    __shared__ unsigned int wmax[8];
    if (lane == 0) wmax[wid] = mymax;
    __syncthreads();
    if (tid == 0) {
        unsigned int m = wmax[0];
#pragma unroll
        for (int i = 1; i < 8; i++) m = max(m, wmax[i]);
        atomicMax(&g_maxkey, m);
    }
}

// ---------------- tilesel: cutabs = 512th-largest tile max + compact qualifying tile list ----------------
__global__ void __launch_bounds__(1024) tilesel_kernel() {
    __shared__ unsigned int h[WINBINS];
    __shared__ unsigned int pfx[WINBINS];
    __shared__ unsigned int s_cut;
    int t = threadIdx.x;
    if (t < WINBINS) h[t] = 0;
    __syncthreads();
    unsigned int maxk16 = g_maxkey >> 16;
    for (int i = t; i < NTILES; i += 1024) {
        unsigned int rel = maxk16 - (unsigned int)g_tilemax[i];
        if (rel < WINBINS) atomicAdd(&h[rel], 1u);
    }
    __syncthreads();
    if (t < WINBINS) pfx[t] = h[t];
    __syncthreads();
    for (int off = 1; off < WINBINS; off <<= 1) {
        unsigned int v = 0;
        if (t < WINBINS && t >= off) v = pfx[t - off];
        __syncthreads();
        if (t < WINBINS) pfx[t] += v;
        __syncthreads();
    }
    if (t < WINBINS) {
        if (pfx[t] >= TOPK && (t == 0 || pfx[t - 1] < TOPK))
            s_cut = maxk16 - (unsigned int)t;
        if (t == WINBINS - 1 && pfx[t] < TOPK)
            s_cut = maxk16 - (unsigned int)(WINBINS - 1);
    }
    __syncthreads();
    unsigned int cut = s_cut;
    if (t == 0) g_cutabs = cut;
    // compact qualifying tiles
    for (int i = t; i < NTILES; i += 1024) {
        if ((unsigned int)g_tilemax[i] >= cut) {
            unsigned int pos = atomicAdd(&g_tileq_count, 1u);
            if (pos < NTILES) g_tileq[pos] = (unsigned int)i;
        }
    }
}

// ---------------- candidate collection: one warp per tile-quarter, grid-strided ----------------
__global__ void __launch_bounds__(256) cand_kernel(const float* __restrict__ C) {
    unsigned int cutabs = g_cutabs;
    unsigned int ntq = g_tileq_count;
    if (ntq > NTILES) ntq = NTILES;
    unsigned int nunits = ntq * 4;   // 4 quarters (16 rows each) per 64x32 tile
    int lane = threadIdx.x & 31;
    unsigned int warp = (blockIdx.x * blockDim.x + threadIdx.x) >> 5;
    unsigned int nwarp = (gridDim.x * blockDim.x) >> 5;
    int r4 = lane >> 3;           // 0..3 row within 4-row pass
    int c8 = (lane & 7) * 4;      // float4 column start
    for (unsigned int u = warp; u < nunits; u += nwarp) {
        unsigned int tt = g_tileq[u >> 2];
        int q = (int)(u & 3);
        int m0 = (int)(tt >> 8) * 64 + q * 16;
        int n0 = (int)(tt & 255) * 32;
#pragma unroll
        for (int it = 0; it < 4; it++) {
            size_t off = (size_t)(m0 + it * 4 + r4) * N_DIM + n0 + c8;
            float4 v = *(const float4*)(C + off);
            float vv[4] = {v.x, v.y, v.z, v.w};
#pragma unroll
            for (int j = 0; j < 4; j++) {
                if ((fkey(vv[j]) >> 16) >= cutabs) {
                    unsigned int pos = atomicAdd(&g_cand_count, 1u);
                    if (pos < CAND_CAP) g_cand_idx[pos] = (unsigned int)(off + j);
                }
            }
        }
    }
}

// ---------------- refine: exact fp64 dot per candidate ----------------
__global__ void refine_kernel() {
    unsigned int count = g_cand_count;
    if (count > CAND_CAP) count = CAND_CAP;
    unsigned int warp = (blockIdx.x * blockDim.x + threadIdx.x) >> 5;
    unsigned int nwarp = (gridDim.x * blockDim.x) >> 5;
    int lane = threadIdx.x & 31;
    for (unsigned int c = warp; c < count; c += nwarp) {
        unsigned int idx = g_cand_idx[c];
        const float* a = g_md0f + (size_t)(idx >> 13) * HID;
        const float* b = g_md1f + (size_t)(idx & 8191u) * HID;
        double s = 0.0;
#pragma unroll
        for (int k = 0; k < HID / 32; k++)
            s += (double)a[k * 32 + lane] * (double)b[k * 32 + lane];
#pragma unroll
        for (int o = 16; o > 0; o >>= 1)
            s += __shfl_xor_sync(0xffffffffu, s, o);
        if (lane == 0) g_cand_ref[c] = s;
    }
}

// ---------------- rank-select on refined values (deterministic) ----------------
__global__ void __launch_bounds__(256) rank_kernel(float* __restrict__ idx_out) {
    unsigned int count = g_cand_count;
    if (count > CAND_CAP) count = CAND_CAP;
    unsigned int stride = gridDim.x * blockDim.x;
    for (unsigned int i = blockIdx.x * blockDim.x + threadIdx.x; i < count; i += stride) {
        double vi = g_cand_ref[i];
        unsigned int ii = g_cand_idx[i];
        unsigned int rank = 0;
        for (unsigned int j = 0; j < count; j++) {
            double vj = g_cand_ref[j];
            unsigned int ij = g_cand_idx[j];
            if (vj > vi || (vj == vi && ij < ii)) rank++;
        }
        if (rank < TOPK) {
            idx_out[rank * 2 + 0] = (float)(ii >> 13);
            idx_out[rank * 2 + 1] = (float)(ii & 8191u);
        }
    }
}

// ---------------- launch ----------------
extern "C" void kernel_launch(void* const* d_in, const int* in_sizes, int n_in,
                              void* d_out, int out_size) {
    const float* desc0 = (const float*)d_in[0];
    const float* desc1 = (const float*)d_in[1];
    const float* W0a = (const float*)d_in[2];
    const float* b0a = (const float*)d_in[3];
    const float* W0b = (const float*)d_in[4];
    const float* b0b = (const float*)d_in[5];
    const float* W1a = (const float*)d_in[6];
    const float* b1a = (const float*)d_in[7];
    const float* W1b = (const float*)d_in[8];
    const float* b1b = (const float*)d_in[9];

    float* out = (float*)d_out;
    long long simN = (long long)M_DIM * N_DIM;
    long long extra = (long long)out_size - simN;

    float* idx_out = nullptr;
    float* sim = out;
    if (extra >= 2 * TOPK) {  // tuple layout: [indices (TOPK*2)] [sim (M*N)]
        idx_out = out;
        sim = out + extra;
    }

    cudaFuncSetAttribute(gemm_mma_kernel,
                         cudaFuncAttributeMaxDynamicSharedMemorySize, GSMEM_BYTES);

    mlp_kernel<<<512, 256>>>(desc0, desc1, W0a, b0a, W0b, b0b, W1a, b1a, W1b, b1b);
    gemm_mma_kernel<<<dim3(N_DIM / 128, M_DIM / 128), 256, GSMEM_BYTES>>>(sim);

    if (idx_out) {
        tilesel_kernel<<<1, 1024>>>();
        cand_kernel<<<256, 256>>>(sim);
        refine_kernel<<<128, 256>>>();
        rank_kernel<<<64, 256>>>(idx_out);
    }
}

// round 16
// speedup vs baseline: 13.1335x; 1.1523x over previous
#include <cuda_runtime.h>
#include <cuda_fp16.h>
#include <cstdint>

#define M_DIM 8192
#define N_DIM 8192
#define IN_DIM 128
#define HID 256
#define TOPK 512
#define WINBINS 512
#define CAND_CAP (1 << 16)
#define NTILES (128 * 256)   // 64x32 warp tiles

// ---------------- device scratch (no allocations allowed) ----------------
__device__ __half g_md0h[M_DIM * HID];
__device__ __half g_md1h[N_DIM * HID];
__device__ __half g_md1l[N_DIM * HID];
__device__ float g_md0f[M_DIM * HID];
__device__ float g_md1f[N_DIM * HID];
__device__ unsigned short g_tilemax[NTILES];   // per 64x32 tile key max
__device__ unsigned int g_maxkey;
__device__ unsigned int g_cutabs;              // margined 16-bit key threshold
__device__ unsigned int g_tileq[NTILES];       // qualifying tile ids
__device__ unsigned int g_tileq_count;
__device__ unsigned int g_cand_count;
__device__ unsigned int g_cand_idx[CAND_CAP];
__device__ double g_cand_ref[CAND_CAP];

__device__ __forceinline__ unsigned int fkey(float v) {
    unsigned int u = __float_as_uint(v);
    return (u & 0x80000000u) ? ~u : (u | 0x80000000u);
}

// ---------------- MLP (both descriptors in one grid; block 0 resets scalars) ----------------
__global__ void __launch_bounds__(256) mlp_kernel(
    const float* __restrict__ x0, const float* __restrict__ x1,
    const float* __restrict__ W0a, const float* __restrict__ b0a,
    const float* __restrict__ W0b, const float* __restrict__ b0b,
    const float* __restrict__ W1a, const float* __restrict__ b1a,
    const float* __restrict__ W1b, const float* __restrict__ b1b)
{
    __shared__ float xs[32 * IN_DIM];
    __shared__ float hs[32 * HID];
    if (blockIdx.x == 0 && threadIdx.x == 0) {
        g_maxkey = 0; g_cand_count = 0; g_tileq_count = 0;
    }

    int which = (blockIdx.x >= 256) ? 1 : 0;
    int blk = blockIdx.x & 255;
    const float* x = which ? x1 : x0;
    const float* Wa = which ? W1a : W0a;
    const float* ba = which ? b1a : b0a;
    const float* Wb = which ? W1b : W0b;
    const float* bb = which ? b1b : b0b;
    __half* outh = which ? g_md1h : g_md0h;
    float* outf = which ? g_md1f : g_md0f;

    int tid = threadIdx.x;
    const float* xb = x + (size_t)blk * 32 * IN_DIM;

    {
        const float4* src = (const float4*)xb;
        float4* dst = (float4*)xs;
        for (int i = tid; i < 32 * IN_DIM / 4; i += 256) dst[i] = src[i];
    }
    __syncthreads();

    float acc[32];
    float bav = ba[tid];
#pragma unroll
    for (int r = 0; r < 32; r++) acc[r] = bav;

    const float4* xs4 = (const float4*)xs;
    for (int k = 0; k < IN_DIM; k += 4) {
        float w0 = Wa[(k + 0) * HID + tid];
        float w1 = Wa[(k + 1) * HID + tid];
        float w2 = Wa[(k + 2) * HID + tid];
        float w3 = Wa[(k + 3) * HID + tid];
#pragma unroll
        for (int r = 0; r < 32; r++) {
            float4 xv = xs4[r * (IN_DIM / 4) + (k >> 2)];
            acc[r] += xv.x * w0; acc[r] += xv.y * w1;
            acc[r] += xv.z * w2; acc[r] += xv.w * w3;
        }
    }
#pragma unroll
    for (int r = 0; r < 32; r++) hs[r * HID + tid] = fmaxf(acc[r], 0.0f);
    __syncthreads();

    float bbv = bb[tid];
#pragma unroll
    for (int r = 0; r < 32; r++) acc[r] = bbv;

    const float4* hs4 = (const float4*)hs;
    for (int k = 0; k < HID; k += 4) {
        float w0 = Wb[(k + 0) * HID + tid];
        float w1 = Wb[(k + 1) * HID + tid];
        float w2 = Wb[(k + 2) * HID + tid];
        float w3 = Wb[(k + 3) * HID + tid];
#pragma unroll
        for (int r = 0; r < 32; r++) {
            float4 hv = hs4[r * (HID / 4) + (k >> 2)];
            acc[r] += hv.x * w0; acc[r] += hv.y * w1;
            acc[r] += hv.z * w2; acc[r] += hv.w * w3;
        }
    }
#pragma unroll
    for (int r = 0; r < 32; r++) {
        float v = acc[r];
        __half hi = __float2half_rn(v);
        size_t o = ((size_t)blk * 32 + r) * HID + tid;
        outh[o] = hi;
        outf[o] = v;
        if (which) g_md1l[o] = __float2half_rn(v - __half2float(hi));
    }
}

// ---------------- fp16 2-term NT GEMM (ah*bh + ah*bl), BK=32, 2 CTAs/SM ----------------
#define BK 32
#define PITCH 40                       // halves per smem row (80B: 20-word rows -> 4-bank skew)
#define ROWB (PITCH * 2)               // 80 bytes
#define PLANE_BYTES (128 * ROWB)       // 10240
#define BUF_BYTES (3 * PLANE_BYTES)    // 30720 (Ah, Bh, Bl)
#define GSMEM_BYTES (2 * BUF_BYTES)    // 61440

__device__ __forceinline__ uint32_t smem_u32(const void* p) {
    uint32_t a;
    asm("{ .reg .u64 t; cvta.to.shared.u64 t, %1; cvt.u32.u64 %0, t; }" : "=r"(a) : "l"(p));
    return a;
}
__device__ __forceinline__ void cp16(uint32_t dst, const void* src) {
    asm volatile("cp.async.cg.shared.global [%0], [%1], 16;" :: "r"(dst), "l"(src) : "memory");
}
__device__ __forceinline__ void cp_commit() { asm volatile("cp.async.commit_group;" ::: "memory"); }
template <int N>
__device__ __forceinline__ void cp_wait() { asm volatile("cp.async.wait_group %0;" :: "n"(N) : "memory"); }

__device__ __forceinline__ void ldsm_x4(uint32_t& r0, uint32_t& r1, uint32_t& r2, uint32_t& r3,
                                        uint32_t addr) {
    asm volatile("ldmatrix.sync.aligned.m8n8.x4.shared.b16 {%0,%1,%2,%3}, [%4];"
                 : "=r"(r0), "=r"(r1), "=r"(r2), "=r"(r3) : "r"(addr));
}
__device__ __forceinline__ void ldsm_x2(uint32_t& r0, uint32_t& r1, uint32_t addr) {
    asm volatile("ldmatrix.sync.aligned.m8n8.x2.shared.b16 {%0,%1}, [%2];"
                 : "=r"(r0), "=r"(r1) : "r"(addr));
}

__device__ __forceinline__ void mma16816(float* d, uint32_t a0, uint32_t a1, uint32_t a2,
                                         uint32_t a3, uint32_t b0, uint32_t b1) {
    asm volatile(
        "mma.sync.aligned.m16n8k16.row.col.f32.f16.f16.f32 "
        "{%0,%1,%2,%3}, {%4,%5,%6,%7}, {%8,%9}, {%0,%1,%2,%3};"
        : "+f"(d[0]), "+f"(d[1]), "+f"(d[2]), "+f"(d[3])
        : "r"(a0), "r"(a1), "r"(a2), "r"(a3), "r"(b0), "r"(b1));
}

__global__ void __launch_bounds__(256, 2) gemm_mma_kernel(float* __restrict__ C) {
    extern __shared__ char smem[];
    uint32_t sb = smem_u32(smem);

    int tid = threadIdx.x;
    int wid = tid >> 5;
    int lane = tid & 31;
    int gid = lane >> 2;
    int tig = lane & 3;
    int m0 = blockIdx.y * 128;
    int n0 = blockIdx.x * 128;
    int wm = (wid >> 2) * 64;
    int wn = (wid & 3) * 32;

    float acc[4][4][4];
#pragma unroll
    for (int i = 0; i < 4; i++)
#pragma unroll
        for (int j = 0; j < 4; j++)
#pragma unroll
            for (int k = 0; k < 4; k++) acc[i][j][k] = 0.0f;

    const __half* planes_g[3] = {g_md0h, g_md1h, g_md1l};

    // one BK=32 chunk: 3 planes x 128 rows x 64B = 1536 cp16 / 256 thr = 6 each
    auto issue_chunk = [&](int kc, int buf) {
        uint32_t base = sb + buf * BUF_BYTES;
#pragma unroll
        for (int p = 0; p < 3; p++) {
            const __half* gp = planes_g[p];
            int row0 = (p == 0) ? m0 : n0;
#pragma unroll
            for (int j = 0; j < 2; j++) {
                int chunk = tid * 2 + j;       // 0..511
                int row = chunk >> 2;
                int seg = chunk & 3;           // 16B segment within 64B row
                uint32_t dst = base + p * PLANE_BYTES + row * ROWB + seg * 16;
                const void* src = gp + (size_t)(row0 + row) * HID + kc * BK + seg * 8;
                cp16(dst, src);
            }
        }
        cp_commit();
    };

    int a_rowadd = (lane & 7) + ((lane >> 3) & 1) * 8;
    int a_seg = (lane >> 4) * 16;
    int b_lane = lane & 15;
    int b_rowadd = b_lane & 7;
    int b_seg = ((b_lane >> 3) & 1) * 16;

    issue_chunk(0, 0);

    const int NCH = HID / BK;  // 8
    for (int kc = 0; kc < NCH; kc++) {
        int buf = kc & 1;
        if (kc + 1 < NCH) {
            issue_chunk(kc + 1, (kc + 1) & 1);
            cp_wait<1>();
        } else {
            cp_wait<0>();
        }
        __syncthreads();

        uint32_t bufb = sb + buf * BUF_BYTES;
        uint32_t pAh = bufb + 0 * PLANE_BYTES;
        uint32_t pBh = bufb + 1 * PLANE_BYTES;
        uint32_t pBl = bufb + 2 * PLANE_BYTES;

#pragma unroll
        for (int ks = 0; ks < BK / 16; ks++) {
            uint32_t kso = ks * 32;
            uint32_t ah[4][4], bh[4][2], bl[4][2];
#pragma unroll
            for (int mt = 0; mt < 4; mt++) {
                uint32_t ro = (uint32_t)(wm + mt * 16 + a_rowadd) * ROWB + kso + a_seg;
                ldsm_x4(ah[mt][0], ah[mt][1], ah[mt][2], ah[mt][3], pAh + ro);
            }
#pragma unroll
            for (int nt = 0; nt < 4; nt++) {
                uint32_t ro = (uint32_t)(wn + nt * 8 + b_rowadd) * ROWB + kso + b_seg;
                ldsm_x2(bh[nt][0], bh[nt][1], pBh + ro);
                ldsm_x2(bl[nt][0], bl[nt][1], pBl + ro);
            }
#pragma unroll
            for (int mt = 0; mt < 4; mt++)
#pragma unroll
                for (int nt = 0; nt < 4; nt++) {
                    mma16816(acc[mt][nt], ah[mt][0], ah[mt][1], ah[mt][2], ah[mt][3],
                             bh[nt][0], bh[nt][1]);
                    mma16816(acc[mt][nt], ah[mt][0], ah[mt][1], ah[mt][2], ah[mt][3],
                             bl[nt][0], bl[nt][1]);
                }
        }
        __syncthreads();
    }

    // epilogue: store C + tile max + fused global max
    unsigned int mymax = 0;
#pragma unroll
    for (int mt = 0; mt < 4; mt++) {
        int r0 = m0 + wm + mt * 16 + gid;
#pragma unroll
        for (int nt = 0; nt < 4; nt++) {
            int col = n0 + wn + nt * 8 + 2 * tig;
            size_t o0 = (size_t)r0 * N_DIM + col;
            size_t o1 = (size_t)(r0 + 8) * N_DIM + col;
            *(float2*)(C + o0) = make_float2(acc[mt][nt][0], acc[mt][nt][1]);
            *(float2*)(C + o1) = make_float2(acc[mt][nt][2], acc[mt][nt][3]);
            unsigned int k0 = fkey(acc[mt][nt][0]), k1 = fkey(acc[mt][nt][1]);
            unsigned int k2 = fkey(acc[mt][nt][2]), k3 = fkey(acc[mt][nt][3]);
            mymax = max(max(mymax, max(k0, k1)), max(k2, k3));
        }
    }
#pragma unroll
    for (int s = 16; s > 0; s >>= 1)
        mymax = max(mymax, __shfl_xor_sync(0xffffffffu, mymax, s));

    if (lane == 0) {
        int mt = blockIdx.y * 2 + (wid >> 2);
        int nt = blockIdx.x * 4 + (wid & 3);
        g_tilemax[mt * 256 + nt] = (unsigned short)(mymax >> 16);
    }

    __shared__ unsigned int wmax[8];
    if (lane == 0) wmax[wid] = mymax;
    __syncthreads();
    if (tid == 0) {
        unsigned int m = wmax[0];
#pragma unroll
        for (int i = 1; i < 8; i++) m = max(m, wmax[i]);
        atomicMax(&g_maxkey, m);
    }
}

// ---------------- tilesel: cutabs = 512th-largest tile max MINUS 1-bin safety margin ----------------
__global__ void __launch_bounds__(1024) tilesel_kernel() {
    __shared__ unsigned int h[WINBINS];
    __shared__ unsigned int pfx[WINBINS];
    __shared__ unsigned int s_cut;
    int t = threadIdx.x;
    if (t < WINBINS) h[t] = 0;
    __syncthreads();
    unsigned int maxk16 = g_maxkey >> 16;
    for (int i = t; i < NTILES; i += 1024) {
        unsigned int rel = maxk16 - (unsigned int)g_tilemax[i];
        if (rel < WINBINS) atomicAdd(&h[rel], 1u);
    }
    __syncthreads();
    if (t < WINBINS) pfx[t] = h[t];
    __syncthreads();
    for (int off = 1; off < WINBINS; off <<= 1) {
        unsigned int v = 0;
        if (t < WINBINS && t >= off) v = pfx[t - off];
        __syncthreads();
        if (t < WINBINS) pfx[t] += v;
        __syncthreads();
    }
    if (t < WINBINS) {
        if (pfx[t] >= TOPK && (t == 0 || pfx[t - 1] < TOPK))
            s_cut = maxk16 - (unsigned int)t;
        if (t == WINBINS - 1 && pfx[t] < TOPK)
            s_cut = maxk16 - (unsigned int)(WINBINS - 1);
    }
    __syncthreads();
    unsigned int cut = s_cut;
    cut = (cut > 0) ? (cut - 1) : 0;   // 1-bin margin: absorbs approx-vs-exact key shifts
    if (t == 0) g_cutabs = cut;
    for (int i = t; i < NTILES; i += 1024) {
        if ((unsigned int)g_tilemax[i] >= cut) {
            unsigned int pos = atomicAdd(&g_tileq_count, 1u);
            if (pos < NTILES) g_tileq[pos] = (unsigned int)i;
        }
    }
}

// ---------------- candidate collection: one warp per tile-quarter, grid-strided ----------------
__global__ void __launch_bounds__(256) cand_kernel(const float* __restrict__ C) {
    unsigned int cutabs = g_cutabs;
    unsigned int ntq = g_tileq_count;
    if (ntq > NTILES) ntq = NTILES;
    unsigned int nunits = ntq * 4;
    int lane = threadIdx.x & 31;
    unsigned int warp = (blockIdx.x * blockDim.x + threadIdx.x) >> 5;
    unsigned int nwarp = (gridDim.x * blockDim.x) >> 5;
    int r4 = lane >> 3;
    int c8 = (lane & 7) * 4;
    for (unsigned int u = warp; u < nunits; u += nwarp) {
        unsigned int tt = g_tileq[u >> 2];
        int q = (int)(u & 3);
        int m0 = (int)(tt >> 8) * 64 + q * 16;
        int n0 = (int)(tt & 255) * 32;
#pragma unroll
        for (int it = 0; it < 4; it++) {
            size_t off = (size_t)(m0 + it * 4 + r4) * N_DIM + n0 + c8;
            float4 v = *(const float4*)(C + off);
            float vv[4] = {v.x, v.y, v.z, v.w};
#pragma unroll
            for (int j = 0; j < 4; j++) {
                if ((fkey(vv[j]) >> 16) >= cutabs) {
                    unsigned int pos = atomicAdd(&g_cand_count, 1u);
                    if (pos < CAND_CAP) g_cand_idx[pos] = (unsigned int)(off + j);
                }
            }
        }
    }
}

// ---------------- refine: exact fp64 dot per candidate ----------------
__global__ void refine_kernel() {
    unsigned int count = g_cand_count;
    if (count > CAND_CAP) count = CAND_CAP;
    unsigned int warp = (blockIdx.x * blockDim.x + threadIdx.x) >> 5;
    unsigned int nwarp = (gridDim.x * blockDim.x) >> 5;
    int lane = threadIdx.x & 31;
    for (unsigned int c = warp; c < count; c += nwarp) {
        unsigned int idx = g_cand_idx[c];
        const float* a = g_md0f + (size_t)(idx >> 13) * HID;
        const float* b = g_md1f + (size_t)(idx & 8191u) * HID;
        double s = 0.0;
#pragma unroll
        for (int k = 0; k < HID / 32; k++)
            s += (double)a[k * 32 + lane] * (double)b[k * 32 + lane];
#pragma unroll
        for (int o = 16; o > 0; o >>= 1)
            s += __shfl_xor_sync(0xffffffffu, s, o);
        if (lane == 0) g_cand_ref[c] = s;
    }
}

// ---------------- rank-select on refined values (deterministic) ----------------
__global__ void __launch_bounds__(256) rank_kernel(float* __restrict__ idx_out) {
    unsigned int count = g_cand_count;
    if (count > CAND_CAP) count = CAND_CAP;
    unsigned int stride = gridDim.x * blockDim.x;
    for (unsigned int i = blockIdx.x * blockDim.x + threadIdx.x; i < count; i += stride) {
        double vi = g_cand_ref[i];
        unsigned int ii = g_cand_idx[i];
        unsigned int rank = 0;
        for (unsigned int j = 0; j < count; j++) {
            double vj = g_cand_ref[j];
            unsigned int ij = g_cand_idx[j];
            if (vj > vi || (vj == vi && ij < ii)) rank++;
        }
        if (rank < TOPK) {
            idx_out[rank * 2 + 0] = (float)(ii >> 13);
            idx_out[rank * 2 + 1] = (float)(ii & 8191u);
        }
    }
}

// ---------------- launch ----------------
extern "C" void kernel_launch(void* const* d_in, const int* in_sizes, int n_in,
                              void* d_out, int out_size) {
    const float* desc0 = (const float*)d_in[0];
    const float* desc1 = (const float*)d_in[1];
    const float* W0a = (const float*)d_in[2];
    const float* b0a = (const float*)d_in[3];
    const float* W0b = (const float*)d_in[4];
    const float* b0b = (const float*)d_in[5];
    const float* W1a = (const float*)d_in[6];
    const float* b1a = (const float*)d_in[7];
    const float* W1b = (const float*)d_in[8];
    const float* b1b = (const float*)d_in[9];

    float* out = (float*)d_out;
    long long simN = (long long)M_DIM * N_DIM;
    long long extra = (long long)out_size - simN;

    float* idx_out = nullptr;
    float* sim = out;
    if (extra >= 2 * TOPK) {  // tuple layout: [indices (TOPK*2)] [sim (M*N)]
        idx_out = out;
        sim = out + extra;
    }

    cudaFuncSetAttribute(gemm_mma_kernel,
                         cudaFuncAttributeMaxDynamicSharedMemorySize, GSMEM_BYTES);

    mlp_kernel<<<512, 256>>>(desc0, desc1, W0a, b0a, W0b, b0b, W1a, b1a, W1b, b1b);
    gemm_mma_kernel<<<dim3(N_DIM / 128, M_DIM / 128), 256, GSMEM_BYTES>>>(sim);

    if (idx_out) {
        tilesel_kernel<<<1, 1024>>>();
        cand_kernel<<<256, 256>>>(sim);
        refine_kernel<<<128, 256>>>();
        rank_kernel<<<64, 256>>>(idx_out);
    }
}

// round 17
// speedup vs baseline: 16.3675x; 1.2462x over previous
#include <cuda_runtime.h>
#include <cuda_fp16.h>
#include <cstdint>

#define M_DIM 8192
#define N_DIM 8192
#define IN_DIM 128
#define HID 256
#define TOPK 512
#define WINBINS 512
#define CAND_CAP (1 << 16)
#define NTILES (128 * 256)   // 64x32 warp tiles

// ---------------- device scratch (no allocations allowed) ----------------
__device__ __half g_md0h[M_DIM * HID];
__device__ __half g_md1h[N_DIM * HID];
__device__ float g_md0f[M_DIM * HID];
__device__ float g_md1f[N_DIM * HID];
__device__ unsigned short g_tilemax[NTILES];   // per 64x32 tile key max
__device__ unsigned int g_maxkey;
__device__ unsigned int g_cutabs;              // margined 16-bit key threshold
__device__ unsigned int g_tileq[NTILES];       // qualifying tile ids
__device__ unsigned int g_tileq_count;
__device__ unsigned int g_cand_count;
__device__ unsigned int g_cand_idx[CAND_CAP];
__device__ double g_cand_ref[CAND_CAP];

__device__ __forceinline__ unsigned int fkey(float v) {
    unsigned int u = __float_as_uint(v);
    return (u & 0x80000000u) ? ~u : (u | 0x80000000u);
}

// ---------------- MLP (both descriptors in one grid; block 0 resets scalars) ----------------
__global__ void __launch_bounds__(256) mlp_kernel(
    const float* __restrict__ x0, const float* __restrict__ x1,
    const float* __restrict__ W0a, const float* __restrict__ b0a,
    const float* __restrict__ W0b, const float* __restrict__ b0b,
    const float* __restrict__ W1a, const float* __restrict__ b1a,
    const float* __restrict__ W1b, const float* __restrict__ b1b)
{
    __shared__ float xs[32 * IN_DIM];
    __shared__ float hs[32 * HID];
    if (blockIdx.x == 0 && threadIdx.x == 0) {
        g_maxkey = 0; g_cand_count = 0; g_tileq_count = 0;
    }

    int which = (blockIdx.x >= 256) ? 1 : 0;
    int blk = blockIdx.x & 255;
    const float* x = which ? x1 : x0;
    const float* Wa = which ? W1a : W0a;
    const float* ba = which ? b1a : b0a;
    const float* Wb = which ? W1b : W0b;
    const float* bb = which ? b1b : b0b;
    __half* outh = which ? g_md1h : g_md0h;
    float* outf = which ? g_md1f : g_md0f;

    int tid = threadIdx.x;
    const float* xb = x + (size_t)blk * 32 * IN_DIM;

    {
        const float4* src = (const float4*)xb;
        float4* dst = (float4*)xs;
        for (int i = tid; i < 32 * IN_DIM / 4; i += 256) dst[i] = src[i];
    }
    __syncthreads();

    float acc[32];
    float bav = ba[tid];
#pragma unroll
    for (int r = 0; r < 32; r++) acc[r] = bav;

    const float4* xs4 = (const float4*)xs;
    for (int k = 0; k < IN_DIM; k += 4) {
        float w0 = Wa[(k + 0) * HID + tid];
        float w1 = Wa[(k + 1) * HID + tid];
        float w2 = Wa[(k + 2) * HID + tid];
        float w3 = Wa[(k + 3) * HID + tid];
#pragma unroll
        for (int r = 0; r < 32; r++) {
            float4 xv = xs4[r * (IN_DIM / 4) + (k >> 2)];
            acc[r] += xv.x * w0; acc[r] += xv.y * w1;
            acc[r] += xv.z * w2; acc[r] += xv.w * w3;
        }
    }
#pragma unroll
    for (int r = 0; r < 32; r++) hs[r * HID + tid] = fmaxf(acc[r], 0.0f);
    __syncthreads();

    float bbv = bb[tid];
#pragma unroll
    for (int r = 0; r < 32; r++) acc[r] = bbv;

    const float4* hs4 = (const float4*)hs;
    for (int k = 0; k < HID; k += 4) {
        float w0 = Wb[(k + 0) * HID + tid];
        float w1 = Wb[(k + 1) * HID + tid];
        float w2 = Wb[(k + 2) * HID + tid];
        float w3 = Wb[(k + 3) * HID + tid];
#pragma unroll
        for (int r = 0; r < 32; r++) {
            float4 hv = hs4[r * (HID / 4) + (k >> 2)];
            acc[r] += hv.x * w0; acc[r] += hv.y * w1;
            acc[r] += hv.z * w2; acc[r] += hv.w * w3;
        }
    }
#pragma unroll
    for (int r = 0; r < 32; r++) {
        float v = acc[r];
        size_t o = ((size_t)blk * 32 + r) * HID + tid;
        outh[o] = __float2half_rn(v);
        outf[o] = v;
    }
}

// ---------------- fp16 1-term NT GEMM (ah*bh), BK=32, 2 CTAs/SM ----------------
#define BK 32
#define PITCH 40                       // halves per smem row (80B: 20-word rows -> 4-bank skew)
#define ROWB (PITCH * 2)               // 80 bytes
#define PLANE_BYTES (128 * ROWB)       // 10240
#define BUF_BYTES (2 * PLANE_BYTES)    // 20480 (Ah, Bh)
#define GSMEM_BYTES (2 * BUF_BYTES)    // 40960

__device__ __forceinline__ uint32_t smem_u32(const void* p) {
    uint32_t a;
    asm("{ .reg .u64 t; cvta.to.shared.u64 t, %1; cvt.u32.u64 %0, t; }" : "=r"(a) : "l"(p));
    return a;
}
__device__ __forceinline__ void cp16(uint32_t dst, const void* src) {
    asm volatile("cp.async.cg.shared.global [%0], [%1], 16;" :: "r"(dst), "l"(src) : "memory");
}
__device__ __forceinline__ void cp_commit() { asm volatile("cp.async.commit_group;" ::: "memory"); }
template <int N>
__device__ __forceinline__ void cp_wait() { asm volatile("cp.async.wait_group %0;" :: "n"(N) : "memory"); }

__device__ __forceinline__ void ldsm_x4(uint32_t& r0, uint32_t& r1, uint32_t& r2, uint32_t& r3,
                                        uint32_t addr) {
    asm volatile("ldmatrix.sync.aligned.m8n8.x4.shared.b16 {%0,%1,%2,%3}, [%4];"
                 : "=r"(r0), "=r"(r1), "=r"(r2), "=r"(r3) : "r"(addr));
}
__device__ __forceinline__ void ldsm_x2(uint32_t& r0, uint32_t& r1, uint32_t addr) {
    asm volatile("ldmatrix.sync.aligned.m8n8.x2.shared.b16 {%0,%1}, [%2];"
                 : "=r"(r0), "=r"(r1) : "r"(addr));
}

__device__ __forceinline__ void mma16816(float* d, uint32_t a0, uint32_t a1, uint32_t a2,
                                         uint32_t a3, uint32_t b0, uint32_t b1) {
    asm volatile(
        "mma.sync.aligned.m16n8k16.row.col.f32.f16.f16.f32 "
        "{%0,%1,%2,%3}, {%4,%5,%6,%7}, {%8,%9}, {%0,%1,%2,%3};"
        : "+f"(d[0]), "+f"(d[1]), "+f"(d[2]), "+f"(d[3])
        : "r"(a0), "r"(a1), "r"(a2), "r"(a3), "r"(b0), "r"(b1));
}

__global__ void __launch_bounds__(256, 2) gemm_mma_kernel(float* __restrict__ C) {
    extern __shared__ char smem[];
    uint32_t sb = smem_u32(smem);

    int tid = threadIdx.x;
    int wid = tid >> 5;
    int lane = tid & 31;
    int gid = lane >> 2;
    int tig = lane & 3;
    int m0 = blockIdx.y * 128;
    int n0 = blockIdx.x * 128;
    int wm = (wid >> 2) * 64;
    int wn = (wid & 3) * 32;

    float acc[4][4][4];
#pragma unroll
    for (int i = 0; i < 4; i++)
#pragma unroll
        for (int j = 0; j < 4; j++)
#pragma unroll
            for (int k = 0; k < 4; k++) acc[i][j][k] = 0.0f;

    const __half* planes_g[2] = {g_md0h, g_md1h};

    // one BK=32 chunk: 2 planes x 128 rows x 64B = 1024 cp16 / 256 thr = 4 each
    auto issue_chunk = [&](int kc, int buf) {
        uint32_t base = sb + buf * BUF_BYTES;
#pragma unroll
        for (int p = 0; p < 2; p++) {
            const __half* gp = planes_g[p];
            int row0 = (p == 0) ? m0 : n0;
#pragma unroll
            for (int j = 0; j < 2; j++) {
                int chunk = tid * 2 + j;       // 0..511
                int row = chunk >> 2;
                int seg = chunk & 3;           // 16B segment within 64B row
                uint32_t dst = base + p * PLANE_BYTES + row * ROWB + seg * 16;
                const void* src = gp + (size_t)(row0 + row) * HID + kc * BK + seg * 8;
                cp16(dst, src);
            }
        }
        cp_commit();
    };

    int a_rowadd = (lane & 7) + ((lane >> 3) & 1) * 8;
    int a_seg = (lane >> 4) * 16;
    int b_lane = lane & 15;
    int b_rowadd = b_lane & 7;
    int b_seg = ((b_lane >> 3) & 1) * 16;

    issue_chunk(0, 0);

    const int NCH = HID / BK;  // 8
    for (int kc = 0; kc < NCH; kc++) {
        int buf = kc & 1;
        if (kc + 1 < NCH) {
            issue_chunk(kc + 1, (kc + 1) & 1);
            cp_wait<1>();
        } else {
            cp_wait<0>();
        }
        __syncthreads();

        uint32_t bufb = sb + buf * BUF_BYTES;
        uint32_t pAh = bufb + 0 * PLANE_BYTES;
        uint32_t pBh = bufb + 1 * PLANE_BYTES;

#pragma unroll
        for (int ks = 0; ks < BK / 16; ks++) {
            uint32_t kso = ks * 32;
            uint32_t ah[4][4], bh[4][2];
#pragma unroll
            for (int mt = 0; mt < 4; mt++) {
                uint32_t ro = (uint32_t)(wm + mt * 16 + a_rowadd) * ROWB + kso + a_seg;
                ldsm_x4(ah[mt][0], ah[mt][1], ah[mt][2], ah[mt][3], pAh + ro);
            }
#pragma unroll
            for (int nt = 0; nt < 4; nt++) {
                uint32_t ro = (uint32_t)(wn + nt * 8 + b_rowadd) * ROWB + kso + b_seg;
                ldsm_x2(bh[nt][0], bh[nt][1], pBh + ro);
            }
#pragma unroll
            for (int mt = 0; mt < 4; mt++)
#pragma unroll
                for (int nt = 0; nt < 4; nt++)
                    mma16816(acc[mt][nt], ah[mt][0], ah[mt][1], ah[mt][2], ah[mt][3],
                             bh[nt][0], bh[nt][1]);
        }
        __syncthreads();
    }

    // epilogue: store C + tile max + fused global max
    unsigned int mymax = 0;
#pragma unroll
    for (int mt = 0; mt < 4; mt++) {
        int r0 = m0 + wm + mt * 16 + gid;
#pragma unroll
        for (int nt = 0; nt < 4; nt++) {
            int col = n0 + wn + nt * 8 + 2 * tig;
            size_t o0 = (size_t)r0 * N_DIM + col;
            size_t o1 = (size_t)(r0 + 8) * N_DIM + col;
            *(float2*)(C + o0) = make_float2(acc[mt][nt][0], acc[mt][nt][1]);
            *(float2*)(C + o1) = make_float2(acc[mt][nt][2], acc[mt][nt][3]);
            unsigned int k0 = fkey(acc[mt][nt][0]), k1 = fkey(acc[mt][nt][1]);
            unsigned int k2 = fkey(acc[mt][nt][2]), k3 = fkey(acc[mt][nt][3]);
            mymax = max(max(mymax, max(k0, k1)), max(k2, k3));
        }
    }
#pragma unroll
    for (int s = 16; s > 0; s >>= 1)
        mymax = max(mymax, __shfl_xor_sync(0xffffffffu, mymax, s));

    if (lane == 0) {
        int mt = blockIdx.y * 2 + (wid >> 2);
        int nt = blockIdx.x * 4 + (wid & 3);
        g_tilemax[mt * 256 + nt] = (unsigned short)(mymax >> 16);
    }

    __shared__ unsigned int wmax[8];
    if (lane == 0) wmax[wid] = mymax;
    __syncthreads();
    if (tid == 0) {
        unsigned int m = wmax[0];
#pragma unroll
        for (int i = 1; i < 8; i++) m = max(m, wmax[i]);
        atomicMax(&g_maxkey, m);
    }
}

// ---------------- tilesel: cutabs = 512th-largest tile max MINUS 1-bin safety margin ----------------
__global__ void __launch_bounds__(1024) tilesel_kernel() {
    __shared__ unsigned int h[WINBINS];
    __shared__ unsigned int pfx[WINBINS];
    __shared__ unsigned int s_cut;
    int t = threadIdx.x;
    if (t < WINBINS) h[t] = 0;
    __syncthreads();
    unsigned int maxk16 = g_maxkey >> 16;
    for (int i = t; i < NTILES; i += 1024) {
        unsigned int rel = maxk16 - (unsigned int)g_tilemax[i];
        if (rel < WINBINS) atomicAdd(&h[rel], 1u);
    }
    __syncthreads();
    if (t < WINBINS) pfx[t] = h[t];
    __syncthreads();
    for (int off = 1; off < WINBINS; off <<= 1) {
        unsigned int v = 0;
        if (t < WINBINS && t >= off) v = pfx[t - off];
        __syncthreads();
        if (t < WINBINS) pfx[t] += v;
        __syncthreads();
    }
    if (t < WINBINS) {
        if (pfx[t] >= TOPK && (t == 0 || pfx[t - 1] < TOPK))
            s_cut = maxk16 - (unsigned int)t;
        if (t == WINBINS - 1 && pfx[t] < TOPK)
            s_cut = maxk16 - (unsigned int)(WINBINS - 1);
    }
    __syncthreads();
    unsigned int cut = s_cut;
    cut = (cut > 0) ? (cut - 1) : 0;   // 1-bin margin: absorbs approx-vs-exact key shifts
    if (t == 0) g_cutabs = cut;
    for (int i = t; i < NTILES; i += 1024) {
        if ((unsigned int)g_tilemax[i] >= cut) {
            unsigned int pos = atomicAdd(&g_tileq_count, 1u);
            if (pos < NTILES) g_tileq[pos] = (unsigned int)i;
        }
    }
}

// ---------------- candidate collection: one warp per tile-quarter, grid-strided ----------------
__global__ void __launch_bounds__(256) cand_kernel(const float* __restrict__ C) {
    unsigned int cutabs = g_cutabs;
    unsigned int ntq = g_tileq_count;
    if (ntq > NTILES) ntq = NTILES;
    unsigned int nunits = ntq * 4;
    int lane = threadIdx.x & 31;
    unsigned int warp = (blockIdx.x * blockDim.x + threadIdx.x) >> 5;
    unsigned int nwarp = (gridDim.x * blockDim.x) >> 5;
    int r4 = lane >> 3;
    int c8 = (lane & 7) * 4;
    for (unsigned int u = warp; u < nunits; u += nwarp) {
        unsigned int tt = g_tileq[u >> 2];
        int q = (int)(u & 3);
        int m0 = (int)(tt >> 8) * 64 + q * 16;
        int n0 = (int)(tt & 255) * 32;
#pragma unroll
        for (int it = 0; it < 4; it++) {
            size_t off = (size_t)(m0 + it * 4 + r4) * N_DIM + n0 + c8;
            float4 v = *(const float4*)(C + off);
            float vv[4] = {v.x, v.y, v.z, v.w};
#pragma unroll
            for (int j = 0; j < 4; j++) {
                if ((fkey(vv[j]) >> 16) >= cutabs) {
                    unsigned int pos = atomicAdd(&g_cand_count, 1u);
                    if (pos < CAND_CAP) g_cand_idx[pos] = (unsigned int)(off + j);
                }
            }
        }
    }
}

// ---------------- refine: exact fp64 dot per candidate ----------------
__global__ void refine_kernel() {
    unsigned int count = g_cand_count;
    if (count > CAND_CAP) count = CAND_CAP;
    unsigned int warp = (blockIdx.x * blockDim.x + threadIdx.x) >> 5;
    unsigned int nwarp = (gridDim.x * blockDim.x) >> 5;
    int lane = threadIdx.x & 31;
    for (unsigned int c = warp; c < count; c += nwarp) {
        unsigned int idx = g_cand_idx[c];
        const float* a = g_md0f + (size_t)(idx >> 13) * HID;
        const float* b = g_md1f + (size_t)(idx & 8191u) * HID;
        double s = 0.0;
#pragma unroll
        for (int k = 0; k < HID / 32; k++)
            s += (double)a[k * 32 + lane] * (double)b[k * 32 + lane];
#pragma unroll
        for (int o = 16; o > 0; o >>= 1)
            s += __shfl_xor_sync(0xffffffffu, s, o);
        if (lane == 0) g_cand_ref[c] = s;
    }
}

// ---------------- rank-select on refined values (deterministic) ----------------
__global__ void __launch_bounds__(256) rank_kernel(float* __restrict__ idx_out) {
    unsigned int count = g_cand_count;
    if (count > CAND_CAP) count = CAND_CAP;
    unsigned int stride = gridDim.x * blockDim.x;
    for (unsigned int i = blockIdx.x * blockDim.x + threadIdx.x; i < count; i += stride) {
        double vi = g_cand_ref[i];
        unsigned int ii = g_cand_idx[i];
        unsigned int rank = 0;
        for (unsigned int j = 0; j < count; j++) {
            double vj = g_cand_ref[j];
            unsigned int ij = g_cand_idx[j];
            if (vj > vi || (vj == vi && ij < ii)) rank++;
        }
        if (rank < TOPK) {
            idx_out[rank * 2 + 0] = (float)(ii >> 13);
            idx_out[rank * 2 + 1] = (float)(ii & 8191u);
        }
    }
}

// ---------------- launch ----------------
extern "C" void kernel_launch(void* const* d_in, const int* in_sizes, int n_in,
                              void* d_out, int out_size) {
    const float* desc0 = (const float*)d_in[0];
    const float* desc1 = (const float*)d_in[1];
    const float* W0a = (const float*)d_in[2];
    const float* b0a = (const float*)d_in[3];
    const float* W0b = (const float*)d_in[4];
    const float* b0b = (const float*)d_in[5];
    const float* W1a = (const float*)d_in[6];
    const float* b1a = (const float*)d_in[7];
    const float* W1b = (const float*)d_in[8];
    const float* b1b = (const float*)d_in[9];

    float* out = (float*)d_out;
    long long simN = (long long)M_DIM * N_DIM;
    long long extra = (long long)out_size - simN;

    float* idx_out = nullptr;
    float* sim = out;
    if (extra >= 2 * TOPK) {  // tuple layout: [indices (TOPK*2)] [sim (M*N)]
        idx_out = out;
        sim = out + extra;
    }

    cudaFuncSetAttribute(gemm_mma_kernel,
                         cudaFuncAttributeMaxDynamicSharedMemorySize, GSMEM_BYTES);

    mlp_kernel<<<512, 256>>>(desc0, desc1, W0a, b0a, W0b, b0b, W1a, b1a, W1b, b1b);
    gemm_mma_kernel<<<dim3(N_DIM / 128, M_DIM / 128), 256, GSMEM_BYTES>>>(sim);

    if (idx_out) {
        tilesel_kernel<<<1, 1024>>>();
        cand_kernel<<<256, 256>>>(sim);
        refine_kernel<<<128, 256>>>();
        rank_kernel<<<64, 256>>>(idx_out);
    }
}